// round 11
// baseline (speedup 1.0000x reference)
#include <cuda_runtime.h>
#include <cuda_fp16.h>
#include <math_constants.h>
#include <stdint.h>

#define LMAX 100000
#define IMAX 10000
#define NMAX 1000000
#define CC 128

// ---------------- static device scratch (zero-initialized at module load) ----------------
__device__ int      g_cnt[LMAX];
__device__ float    g_sum[LMAX * 3];
__device__ float    g_centroid[LMAX * 3];
__device__ int      g_off[LMAX + 1];
__device__ int      g_cursor[LMAX];
__device__ int      g_pids[NMAX];
__device__ int      g_plocal[NMAX];
__device__ float    g_shape_max[(size_t)LMAX * CC];
__device__ float    g_locals_feat[(size_t)LMAX * CC];
__device__ int      g_cnt_i[IMAX];
__device__ unsigned g_gkeys[(size_t)IMAX * CC];
__device__ float    g_gtlc[IMAX * 3];
__device__ float    g_globals[(size_t)IMAX * CC];
__device__ __half   g_W2t[128 * 128];     // W2_shape^T fp16: [c][k] linear
__device__ __half   g_W1lt[128 * 272];    // W1_loc^T fp16, K padded 262->272: [h][k]
__device__ __half   g_W2lt[128 * 128];    // W2_loc^T fp16: [c][k]

// order-preserving float->uint key for atomicMax on signed floats.
// sentinel 0 (zeroed) < fkey(any finite/inf) for all real inputs.
__device__ __forceinline__ unsigned fkey(float f) {
    unsigned b = __float_as_uint(f);
    return (b & 0x80000000u) ? ~b : (b | 0x80000000u);
}
__device__ __forceinline__ float funkey(unsigned k) {
    return (k & 0x80000000u) ? __uint_as_float(k & 0x7fffffffu) : __uint_as_float(~k);
}

// ---------------- launch 1: centroid count + sum ----------------
__global__ void k_count(const float* __restrict__ xyz, const int* __restrict__ l2f, int n) {
    int i = blockIdx.x * blockDim.x + threadIdx.x;
    if (i >= n) return;
    int l = l2f[i];
    atomicAdd(&g_cnt[l], 1);
    atomicAdd(&g_sum[l * 3 + 0], xyz[i * 3 + 0]);
    atomicAdd(&g_sum[l * 3 + 1], xyz[i * 3 + 1]);
    atomicAdd(&g_sum[l * 3 + 2], xyz[i * 3 + 2]);
}

// ---------------- launch 2: weight preps + centroid + cursor zero + exclusive scan ----------------
__global__ void k_scanprep(int L, const float* __restrict__ W2s_,
                           const float* __restrict__ W1l, const float* __restrict__ W2l) {
    __shared__ int wsum[32];
    int tid = threadIdx.x;                 // 1024 threads

    // W2_shape^T fp16 (linear [c][k])
    for (int i = tid; i < 16384; i += 1024) {
        int c = i >> 7, k = i & 127;
        g_W2t[i] = __float2half(W2s_[k * 128 + c]);
    }
    // mlp2 weights
    for (int i = tid; i < 128 * 272; i += 1024) {
        int h = i / 272, k = i - h * 272;
        g_W1lt[i] = (k < 262) ? __float2half(W1l[k * 128 + h]) : __half(0.f);
    }
    for (int i = tid; i < 16384; i += 1024) {
        int c = i >> 7, k = i & 127;
        g_W2lt[i] = __float2half(W2l[k * 128 + c]);
    }
    // centroids + cursor zero
    for (int l = tid; l < L; l += 1024) {
        float inv = 1.f / fmaxf((float)g_cnt[l], 1.f);
        g_centroid[l * 3 + 0] = g_sum[l * 3 + 0] * inv;
        g_centroid[l * 3 + 1] = g_sum[l * 3 + 1] * inv;
        g_centroid[l * 3 + 2] = g_sum[l * 3 + 2] * inv;
        g_cursor[l] = 0;
    }

    // exclusive scan of g_cnt
    int chunk = (L + 1023) >> 10;
    int s = tid * chunk;
    int e = s + chunk; if (e > L) e = L;
    if (s > L) s = L;
    int sum = 0;
    for (int i = s; i < e; i++) sum += g_cnt[i];

    int lane = tid & 31, w = tid >> 5;
    int v = sum;
    #pragma unroll
    for (int o = 1; o < 32; o <<= 1) {
        int t = __shfl_up_sync(0xffffffffu, v, o);
        if (lane >= o) v += t;
    }
    if (lane == 31) wsum[w] = v;
    __syncthreads();
    if (w == 0) {
        int x = wsum[lane];
        #pragma unroll
        for (int o = 1; o < 32; o <<= 1) {
            int t = __shfl_up_sync(0xffffffffu, x, o);
            if (lane >= o) x += t;
        }
        wsum[lane] = x;
    }
    __syncthreads();
    int excl = v - sum + (w > 0 ? wsum[w - 1] : 0);
    int run = excl;
    for (int i = s; i < e; i++) { int c = g_cnt[i]; g_off[i] = run; run += c; }
    if (tid == 1023) g_off[L] = run;
}

// ---------------- launch 3: CSR scatter + zero shape_max / gkeys / cnt_i ----------------
__global__ void k_csr(const int* __restrict__ l2f, int n, int L, int I) {
    int gt = blockIdx.x * blockDim.x + threadIdx.x;
    int stride = gridDim.x * blockDim.x;
    for (int i = gt; i < L * CC; i += stride) g_shape_max[i] = 0.f;
    for (int i = gt; i < I * CC; i += stride) g_gkeys[i] = 0u;
    for (int i = gt; i < I; i += stride) g_cnt_i[i] = 0;
    if (gt < n) {
        int l = l2f[gt];
        int pos = atomicAdd(&g_cursor[l], 1);
        int slot = g_off[l] + pos;
        g_pids[slot] = gt;
        g_plocal[slot] = l;
    }
}

// ---------------- mma / ldmatrix helpers ----------------
__device__ __forceinline__ void mma16816(float* d, const unsigned* a, unsigned b0, unsigned b1) {
    asm volatile(
        "mma.sync.aligned.m16n8k16.row.col.f32.f16.f16.f32 "
        "{%0,%1,%2,%3}, {%4,%5,%6,%7}, {%8,%9}, {%0,%1,%2,%3};"
        : "+f"(d[0]), "+f"(d[1]), "+f"(d[2]), "+f"(d[3])
        : "r"(a[0]), "r"(a[1]), "r"(a[2]), "r"(a[3]), "r"(b0), "r"(b1));
}
__device__ __forceinline__ void ldm_x4(unsigned* r, uint32_t saddr) {
    asm volatile(
        "ldmatrix.sync.aligned.m8n8.x4.shared.b16 {%0,%1,%2,%3}, [%4];"
        : "=r"(r[0]), "=r"(r[1]), "=r"(r[2]), "=r"(r[3]) : "r"(saddr));
}

// ---------------- launch 4 (PROFILED): shape MLP, layer2 via mma.sync ----------------
#define STRH 136
#define SH_SHAPE (128 * STRH * 2 * 2 + (384 + 128 + 128) * 4 + 128 * 4)

__global__ __launch_bounds__(256) void k_shape(
    const float* __restrict__ xyz,
    const float* __restrict__ W1, const float* __restrict__ b1,
    const float* __restrict__ b2, int n)
{
    extern __shared__ char smraw[];
    __half* hA  = (__half*)smraw;                        // [128][STRH]
    __half* W2t = (__half*)(smraw + 128 * STRH * 2);     // [128][STRH]
    float*  outS = (float*)smraw;                        // reuse, [128][128]
    float*  ext = (float*)(smraw + 128 * STRH * 2 * 2);
    float*  W1s = ext;          // [dim][k]
    float*  b1s = ext + 384;
    float*  b2s = ext + 512;
    int*   lidS = (int*)(ext + 640);

    int tid = threadIdx.x;
    int tile0 = blockIdx.x * 128;

    for (int i = tid; i < 384; i += 256) W1s[i] = W1[i];
    if (tid < 128) { b1s[tid] = b1[tid]; b2s[tid] = b2[tid]; }
    __syncthreads();

    // layer1 (fp32 math, fp16 store) + W2t smem copy
    {
        int p = tid & 127, hid = tid >> 7;
        int row = tile0 + p;
        float cx = 0.f, cy = 0.f, cz = 0.f;
        int l = -1;
        bool valid = (row < n);
        if (valid) {
            int pid = g_pids[row];
            l = g_plocal[row];
            cx = xyz[pid * 3 + 0] - g_centroid[l * 3 + 0];
            cy = xyz[pid * 3 + 1] - g_centroid[l * 3 + 1];
            cz = xyz[pid * 3 + 2] - g_centroid[l * 3 + 2];
        }
        if (hid == 0) lidS[p] = l;
        int k0 = hid * 64;
        #pragma unroll 8
        for (int k = k0; k < k0 + 64; k += 2) {
            float h0 = fmaf(cx, W1s[k],   fmaf(cy, W1s[128 + k],   fmaf(cz, W1s[256 + k],   b1s[k])));
            float h1 = fmaf(cx, W1s[k+1], fmaf(cy, W1s[128 + k+1], fmaf(cz, W1s[256 + k+1], b1s[k+1])));
            h0 = valid ? fmaxf(h0, 0.f) : 0.f;
            h1 = valid ? fmaxf(h1, 0.f) : 0.f;
            *(__half2*)&hA[p * STRH + k] = __floats2half2_rn(h0, h1);
        }
        const unsigned* src = (const unsigned*)g_W2t;
        for (int i = tid; i < 8192; i += 256) {
            int c = i >> 6, k2 = (i & 63) << 1;
            *(unsigned*)&W2t[c * STRH + k2] = src[i];
        }
    }
    __syncthreads();

    // tensor-core GEMM: 128x128x128, warps 4(m) x 2(n), ldmatrix fragment loads
    int wid = tid >> 5, lane = tid & 31;
    int m0 = (wid >> 1) * 32, n0 = (wid & 1) * 64;
    int g = lane >> 2, t4 = (lane & 3) * 2;

    uint32_t hA_s  = (uint32_t)__cvta_generic_to_shared(hA);
    uint32_t W2t_s = (uint32_t)__cvta_generic_to_shared(W2t);
    uint32_t aAddr = hA_s  + ((m0 + (lane & 15)) * STRH + ((lane >> 4) << 3)) * 2;
    uint32_t bAddr = W2t_s + ((n0 + ((lane >> 4) << 3) + (lane & 7)) * STRH + (((lane >> 3) & 1) << 3)) * 2;

    float acc[2][8][4];
    #pragma unroll
    for (int a = 0; a < 2; a++)
        #pragma unroll
        for (int b_ = 0; b_ < 8; b_++)
            #pragma unroll
            for (int c = 0; c < 4; c++) acc[a][b_][c] = 0.f;

    #pragma unroll
    for (int kk = 0; kk < 128; kk += 16) {
        unsigned af[2][4];
        ldm_x4(af[0], aAddr + kk * 2);
        ldm_x4(af[1], aAddr + kk * 2 + 16 * STRH * 2);
        #pragma unroll
        for (int np = 0; np < 4; np++) {
            unsigned bf[4];
            ldm_x4(bf, bAddr + kk * 2 + np * 16 * STRH * 2);
            mma16816(acc[0][2*np],   af[0], bf[0], bf[1]);
            mma16816(acc[1][2*np],   af[1], bf[0], bf[1]);
            mma16816(acc[0][2*np+1], af[0], bf[2], bf[3]);
            mma16816(acc[1][2*np+1], af[1], bf[2], bf[3]);
        }
    }
    __syncthreads();   // done reading hA/W2t -> reuse as outS

    #pragma unroll
    for (int mt = 0; mt < 2; mt++) {
        #pragma unroll
        for (int nt = 0; nt < 8; nt++) {
            int r0 = m0 + mt * 16 + g;
            int c = n0 + nt * 8 + t4;
            float2 v0, v1;
            v0.x = fmaxf(acc[mt][nt][0] + b2s[c], 0.f);
            v0.y = fmaxf(acc[mt][nt][1] + b2s[c + 1], 0.f);
            v1.x = fmaxf(acc[mt][nt][2] + b2s[c], 0.f);
            v1.y = fmaxf(acc[mt][nt][3] + b2s[c + 1], 0.f);
            *(float2*)&outS[r0 * 128 + c] = v0;
            *(float2*)&outS[(r0 + 8) * 128 + c] = v1;
        }
    }
    __syncthreads();

    // segmented max over sorted locals: interior plain-store, boundary atomic.
    if (tid < 128) {
        int c = tid;
        int cur = -2, s = 0;
        float m = 0.f;
        for (int r = 0; r < 128; r++) {
            int l = lidS[r];
            float v = outS[r * 128 + c];
            if (l != cur) {
                if (cur >= 0) {
                    float* dst = &g_shape_max[(size_t)cur * CC + c];
                    if (s > 0) *dst = m;
                    else atomicMax((int*)dst, __float_as_int(m));
                }
                cur = l; m = v; s = r;
            } else m = fmaxf(m, v);
        }
        if (cur >= 0)
            atomicMax((int*)&g_shape_max[(size_t)cur * CC + c], __float_as_int(m));
    }
}

// ---------------- launch 5: fg_feat segmax + locals_feat + global key-max ----------------
__global__ void k_featmax(const float* __restrict__ feat, const int* __restrict__ i2l, int L) {
    int gt = blockIdx.x * blockDim.x + threadIdx.x;
    int w = gt >> 5, lane = gt & 31;
    if (w >= L) return;
    int s = g_off[w], e = g_off[w + 1];
    float m0 = -CUDART_INF_F, m1 = m0, m2 = m0, m3 = m0;
    for (int p = s; p < e; p++) {
        const float* row = feat + (size_t)g_pids[p] * CC;
        m0 = fmaxf(m0, row[lane]);
        m1 = fmaxf(m1, row[lane + 32]);
        m2 = fmaxf(m2, row[lane + 64]);
        m3 = fmaxf(m3, row[lane + 96]);
    }
    if (e <= s) { m0 = m1 = m2 = m3 = 0.f; }
    size_t base = (size_t)w * CC;
    float v0 = m0 + g_shape_max[base + lane];
    float v1 = m1 + g_shape_max[base + lane + 32];
    float v2 = m2 + g_shape_max[base + lane + 64];
    float v3 = m3 + g_shape_max[base + lane + 96];
    g_locals_feat[base + lane]      = v0;
    g_locals_feat[base + lane + 32] = v1;
    g_locals_feat[base + lane + 64] = v2;
    g_locals_feat[base + lane + 96] = v3;
    int inst = i2l[w];
    size_t gb = (size_t)inst * CC;
    atomicMax(&g_gkeys[gb + lane],      fkey(v0));
    atomicMax(&g_gkeys[gb + lane + 32], fkey(v1));
    atomicMax(&g_gkeys[gb + lane + 64], fkey(v2));
    atomicMax(&g_gkeys[gb + lane + 96], fkey(v3));
    if (lane == 0) atomicAdd(&g_cnt_i[inst], 1);
}

// ---------------- launch 6: finalize globals + target centers ----------------
__global__ void k_gfin(const int* __restrict__ ils, int I) {
    int idx = blockIdx.x * blockDim.x + threadIdx.x;
    if (idx < I * CC) {
        int i = idx >> 7;
        g_globals[idx] = (g_cnt_i[i] > 0) ? funkey(g_gkeys[idx]) : 0.f;
    }
    if (idx < I * 3) {
        int i = idx / 3, d = idx % 3;
        g_gtlc[idx] = g_centroid[ils[i] * 3 + d];
    }
}

// ---------------- launch 7: locals MLP (mma.sync) + decoder ----------------
#define KF 262
#define KP 272
#define STRL 280
#define SH_MLP2 (2 * 128 * STRL * 2 + (128 + 128 + 1024 + 8) * 4 + 128 * 4)

__global__ __launch_bounds__(256) void k_mlp2(
    const float* __restrict__ b1, const float* __restrict__ b2,
    const float* __restrict__ Wd, const float* __restrict__ bd,
    const int* __restrict__ i2l,
    float* __restrict__ out_tf, float* __restrict__ out_fo, int L)
{
    extern __shared__ char smraw[];
    __half* A1 = (__half*)smraw;                         // [128][STRL]
    __half* B1 = (__half*)(smraw + 128 * STRL * 2);      // [128][STRL]
    float*  ext = (float*)(smraw + 2 * 128 * STRL * 2);
    float* b1L = ext;
    float* b2L = ext + 128;
    float* wdS = ext + 256;
    float* bdS = ext + 1280;
    int*   ilS = (int*)(ext + 1288);
    __half* hA2 = (__half*)smraw;                        // [128][STRH] (phase 2)
    __half* W2s = (__half*)(smraw + 128 * STRL * 2);     // [128][STRH] (phase 2)
    float*  foS = (float*)smraw;                         // [128][133] (phase 3)

    int tid = threadIdx.x;
    int block0 = blockIdx.x * 128;

    if (tid < 128) {
        b1L[tid] = b1[tid];
        b2L[tid] = b2[tid];
        int l = block0 + tid;
        ilS[tid] = (l < L) ? i2l[l] : 0;
    }
    for (int idx = tid; idx < 128 * 7; idx += 256)
        wdS[(idx / 7) * 8 + (idx % 7)] = Wd[idx];
    if (tid < 7) bdS[tid] = bd[tid];
    __syncthreads();

    for (int idx = tid; idx < 128 * KP; idx += 256) {
        int p = idx / KP, k = idx - p * KP;
        int l = block0 + p;
        float v = 0.f;
        if (l < L && k < KF) {
            int inst = ilS[p];
            if (k < 128)       v = g_locals_feat[(size_t)l * CC + k];
            else if (k < 256)  v = g_globals[(size_t)inst * CC + (k - 128)];
            else if (k < 259)  v = g_centroid[l * 3 + (k - 256)];
            else               v = g_gtlc[inst * 3 + (k - 259)];
        }
        A1[p * STRL + k] = __float2half(v);
    }
    {
        const unsigned* src = (const unsigned*)g_W1lt;
        for (int i = tid; i < 128 * (KP / 2); i += 256) {
            int h = i / (KP / 2), k2 = (i - h * (KP / 2)) << 1;
            *(unsigned*)&B1[h * STRL + k2] = src[i];
        }
    }
    __syncthreads();

    int wid = tid >> 5, lane = tid & 31;
    int m0 = (wid >> 1) * 32, n0 = (wid & 1) * 64;
    int g = lane >> 2, t4 = (lane & 3) * 2;

    uint32_t A1_s = (uint32_t)__cvta_generic_to_shared(A1);
    uint32_t B1_s = (uint32_t)__cvta_generic_to_shared(B1);
    uint32_t aOff = ((m0 + (lane & 15)) * STRL + ((lane >> 4) << 3)) * 2;
    uint32_t bOff = ((n0 + ((lane >> 4) << 3) + (lane & 7)) * STRL + (((lane >> 3) & 1) << 3)) * 2;

    float acc[2][8][4];
    #pragma unroll
    for (int a = 0; a < 2; a++)
        #pragma unroll
        for (int b_ = 0; b_ < 8; b_++)
            #pragma unroll
            for (int c = 0; c < 4; c++) acc[a][b_][c] = 0.f;

    #pragma unroll
    for (int kk = 0; kk < KP; kk += 16) {
        unsigned af[2][4];
        ldm_x4(af[0], A1_s + aOff + kk * 2);
        ldm_x4(af[1], A1_s + aOff + kk * 2 + 16 * STRL * 2);
        #pragma unroll
        for (int np = 0; np < 4; np++) {
            unsigned bf[4];
            ldm_x4(bf, B1_s + bOff + kk * 2 + np * 16 * STRL * 2);
            mma16816(acc[0][2*np],   af[0], bf[0], bf[1]);
            mma16816(acc[1][2*np],   af[1], bf[0], bf[1]);
            mma16816(acc[0][2*np+1], af[0], bf[2], bf[3]);
            mma16816(acc[1][2*np+1], af[1], bf[2], bf[3]);
        }
    }
    __syncthreads();

    #pragma unroll
    for (int mt = 0; mt < 2; mt++) {
        #pragma unroll
        for (int nt = 0; nt < 8; nt++) {
            int r0 = m0 + mt * 16 + g;
            int c = n0 + nt * 8 + t4;
            float h00 = fmaxf(acc[mt][nt][0] + b1L[c], 0.f);
            float h01 = fmaxf(acc[mt][nt][1] + b1L[c + 1], 0.f);
            float h10 = fmaxf(acc[mt][nt][2] + b1L[c], 0.f);
            float h11 = fmaxf(acc[mt][nt][3] + b1L[c + 1], 0.f);
            *(__half2*)&hA2[r0 * STRH + c] = __floats2half2_rn(h00, h01);
            *(__half2*)&hA2[(r0 + 8) * STRH + c] = __floats2half2_rn(h10, h11);
        }
    }
    {
        const unsigned* src = (const unsigned*)g_W2lt;
        for (int i = tid; i < 8192; i += 256) {
            int c = i >> 6, k2 = (i & 63) << 1;
            *(unsigned*)&W2s[c * STRH + k2] = src[i];
        }
    }
    __syncthreads();

    #pragma unroll
    for (int a = 0; a < 2; a++)
        #pragma unroll
        for (int b_ = 0; b_ < 8; b_++)
            #pragma unroll
            for (int c = 0; c < 4; c++) acc[a][b_][c] = 0.f;

    uint32_t hA2_s = (uint32_t)__cvta_generic_to_shared(hA2);
    uint32_t W2s_s = (uint32_t)__cvta_generic_to_shared(W2s);
    uint32_t aOff2 = ((m0 + (lane & 15)) * STRH + ((lane >> 4) << 3)) * 2;
    uint32_t bOff2 = ((n0 + ((lane >> 4) << 3) + (lane & 7)) * STRH + (((lane >> 3) & 1) << 3)) * 2;

    #pragma unroll
    for (int kk = 0; kk < 128; kk += 16) {
        unsigned af[2][4];
        ldm_x4(af[0], hA2_s + aOff2 + kk * 2);
        ldm_x4(af[1], hA2_s + aOff2 + kk * 2 + 16 * STRH * 2);
        #pragma unroll
        for (int np = 0; np < 4; np++) {
            unsigned bf[4];
            ldm_x4(bf, W2s_s + bOff2 + kk * 2 + np * 16 * STRH * 2);
            mma16816(acc[0][2*np],   af[0], bf[0], bf[1]);
            mma16816(acc[1][2*np],   af[1], bf[0], bf[1]);
            mma16816(acc[0][2*np+1], af[0], bf[2], bf[3]);
            mma16816(acc[1][2*np+1], af[1], bf[2], bf[3]);
        }
    }
    __syncthreads();

    #pragma unroll
    for (int mt = 0; mt < 2; mt++) {
        #pragma unroll
        for (int nt = 0; nt < 8; nt++) {
            int r0 = m0 + mt * 16 + g;
            int c = n0 + nt * 8 + t4;
            float v00 = fmaxf(acc[mt][nt][0] + b2L[c], 0.f);
            float v01 = fmaxf(acc[mt][nt][1] + b2L[c + 1], 0.f);
            float v10 = fmaxf(acc[mt][nt][2] + b2L[c], 0.f);
            float v11 = fmaxf(acc[mt][nt][3] + b2L[c + 1], 0.f);
            foS[r0 * 133 + c] = v00; foS[r0 * 133 + c + 1] = v01;
            foS[(r0 + 8) * 133 + c] = v10; foS[(r0 + 8) * 133 + c + 1] = v11;
            int l0 = block0 + r0, l1 = block0 + r0 + 8;
            if (l0 < L) { float2 s; s.x = v00; s.y = v01; *(float2*)&out_fo[(size_t)l0 * CC + c] = s; }
            if (l1 < L) { float2 s; s.x = v10; s.y = v11; *(float2*)&out_fo[(size_t)l1 * CC + c] = s; }
        }
    }
    __syncthreads();

    if (tid < 128) {
        int l = block0 + tid;
        if (l < L) {
            float s[7];
            #pragma unroll
            for (int j = 0; j < 7; j++) s[j] = bdS[j];
            for (int c = 0; c < 128; c++) {
                float f = foS[tid * 133 + c];
                #pragma unroll
                for (int j = 0; j < 7; j++) s[j] = fmaf(f, wdS[c * 8 + j], s[j]);
            }
            #pragma unroll
            for (int j = 0; j < 7; j++) out_tf[(size_t)l * 7 + j] = s[j];
        }
    }
}

// ---------------- launch 8: re-zero count/sum for next graph replay ----------------
__global__ void k_clean(int L) {
    int i = blockIdx.x * blockDim.x + threadIdx.x;
    if (i < L) g_cnt[i] = 0;
    if (i < 3 * L) g_sum[i] = 0.f;
}

// ---------------- launch ----------------
extern "C" void kernel_launch(void* const* d_in, const int* in_sizes, int n_in,
                              void* d_out, int out_size) {
    const float* xyz  = (const float*)d_in[0];
    const float* feat = (const float*)d_in[1];
    const float* W1s_ = (const float*)d_in[2];
    const float* b1s_ = (const float*)d_in[3];
    const float* W2s_ = (const float*)d_in[4];
    const float* b2s_ = (const float*)d_in[5];
    const float* W1l  = (const float*)d_in[6];
    const float* b1l  = (const float*)d_in[7];
    const float* W2l  = (const float*)d_in[8];
    const float* b2l  = (const float*)d_in[9];
    const float* Wd   = (const float*)d_in[10];
    const float* bd   = (const float*)d_in[11];
    const int*   l2f  = (const int*)d_in[12];
    const int*   i2l  = (const int*)d_in[13];
    const int*   ils  = (const int*)d_in[14];

    int n = in_sizes[0] / 3;
    int L = in_sizes[13];
    int I = in_sizes[14];

    float* out_tf = (float*)d_out;
    float* out_fo = (float*)d_out + (size_t)L * 7;

    cudaFuncSetAttribute(k_shape, cudaFuncAttributeMaxDynamicSharedMemorySize, SH_SHAPE);
    cudaFuncSetAttribute(k_mlp2,  cudaFuncAttributeMaxDynamicSharedMemorySize, SH_MLP2);

    // g_cnt/g_sum are zero at first call (static init) and re-zeroed by k_clean
    // at the end of every call, so each graph replay starts from the same state.
    k_count<<<(n + 255) / 256, 256>>>(xyz, l2f, n);                                   // 1
    k_scanprep<<<1, 1024>>>(L, W2s_, W1l, W2l);                                       // 2
    k_csr<<<(n + 255) / 256, 256>>>(l2f, n, L, I);                                    // 3
    k_shape<<<(n + 127) / 128, 256, SH_SHAPE>>>(xyz, W1s_, b1s_, b2s_, n);            // 4 <- profiled
    k_featmax<<<(L * 32 + 255) / 256, 256>>>(feat, i2l, L);                           // 5
    k_gfin<<<(I * CC + 255) / 256, 256>>>(ils, I);                                    // 6
    k_mlp2<<<(L + 127) / 128, 256, SH_MLP2>>>(b1l, b2l, Wd, bd, i2l, out_tf, out_fo, L); // 7
    k_clean<<<(3 * L + 255) / 256, 256>>>(L);                                         // 8
}

// round 12
// speedup vs baseline: 1.1644x; 1.1644x over previous
#include <cuda_runtime.h>
#include <cuda_fp16.h>
#include <math_constants.h>
#include <stdint.h>

#define LMAX 100000
#define IMAX 10000
#define NMAX 1000000
#define CC 128

// ---------------- static device scratch (zero-initialized at module load) ----------------
__device__ int      g_cnt[LMAX];
__device__ float    g_sum[LMAX * 3];
__device__ float    g_centroid[LMAX * 3];
__device__ int      g_off[LMAX + 1];
__device__ int      g_cursor[LMAX];
__device__ int      g_pids[NMAX];
__device__ int      g_plocal[NMAX];
__device__ float    g_shape_max[(size_t)LMAX * CC];
__device__ float    g_locals_feat[(size_t)LMAX * CC];
__device__ int      g_cnt_i[IMAX];
__device__ unsigned g_gkeys[(size_t)IMAX * CC];
__device__ float    g_gtlc[IMAX * 3];
__device__ float    g_globals[(size_t)IMAX * CC];
__device__ __half   g_W2t[128 * 128];     // W2_shape^T fp16: [c][k] linear
__device__ __half   g_W1lt[128 * 272];    // W1_loc^T fp16, K padded 262->272: [h][k]
__device__ __half   g_W2lt[128 * 128];    // W2_loc^T fp16: [c][k]

// order-preserving float->uint key for atomicMax on signed floats.
__device__ __forceinline__ unsigned fkey(float f) {
    unsigned b = __float_as_uint(f);
    return (b & 0x80000000u) ? ~b : (b | 0x80000000u);
}
__device__ __forceinline__ float funkey(unsigned k) {
    return (k & 0x80000000u) ? __uint_as_float(k & 0x7fffffffu) : __uint_as_float(~k);
}

// ---------------- launch 1: centroid count + sum ----------------
__global__ void k_count(const float* __restrict__ xyz, const int* __restrict__ l2f, int n) {
    int i = blockIdx.x * blockDim.x + threadIdx.x;
    if (i >= n) return;
    int l = l2f[i];
    atomicAdd(&g_cnt[l], 1);
    atomicAdd(&g_sum[l * 3 + 0], xyz[i * 3 + 0]);
    atomicAdd(&g_sum[l * 3 + 1], xyz[i * 3 + 1]);
    atomicAdd(&g_sum[l * 3 + 2], xyz[i * 3 + 2]);
}

// ---------------- launch 2: exclusive scan of g_cnt + cursor zero (single block) ----------------
__global__ void k_scan(int L) {
    __shared__ int wsum[32];
    int tid = threadIdx.x;                 // 1024 threads
    for (int l = tid; l < L; l += 1024) g_cursor[l] = 0;

    int chunk = (L + 1023) >> 10;
    int s = tid * chunk;
    int e = s + chunk; if (e > L) e = L;
    if (s > L) s = L;
    int sum = 0;
    for (int i = s; i < e; i++) sum += g_cnt[i];

    int lane = tid & 31, w = tid >> 5;
    int v = sum;
    #pragma unroll
    for (int o = 1; o < 32; o <<= 1) {
        int t = __shfl_up_sync(0xffffffffu, v, o);
        if (lane >= o) v += t;
    }
    if (lane == 31) wsum[w] = v;
    __syncthreads();
    if (w == 0) {
        int x = wsum[lane];
        #pragma unroll
        for (int o = 1; o < 32; o <<= 1) {
            int t = __shfl_up_sync(0xffffffffu, x, o);
            if (lane >= o) x += t;
        }
        wsum[lane] = x;
    }
    __syncthreads();
    int excl = v - sum + (w > 0 ? wsum[w - 1] : 0);
    int run = excl;
    for (int i = s; i < e; i++) { int c = g_cnt[i]; g_off[i] = run; run += c; }
    if (tid == 1023) g_off[L] = run;
}

// ---------------- launch 3: CSR scatter + centroid + weight prep + zero (wide grid) ----------------
__global__ void k_csr(const int* __restrict__ l2f,
                      const float* __restrict__ W2s_, const float* __restrict__ W1l,
                      const float* __restrict__ W2l,
                      int n, int L, int I) {
    int gt = blockIdx.x * blockDim.x + threadIdx.x;
    int stride = gridDim.x * blockDim.x;

    // weight conversions (parallel)
    for (int i = gt; i < 16384; i += stride) {
        int c = i >> 7, k = i & 127;
        g_W2t[i]  = __float2half(W2s_[k * 128 + c]);
        g_W2lt[i] = __float2half(W2l[k * 128 + c]);
    }
    for (int i = gt; i < 128 * 272; i += stride) {
        int h = i / 272, k = i - h * 272;
        g_W1lt[i] = (k < 262) ? __float2half(W1l[k * 128 + h]) : __half(0.f);
    }
    // centroids (g_cnt/g_sum last read here)
    for (int l = gt; l < L; l += stride) {
        float inv = 1.f / fmaxf((float)g_cnt[l], 1.f);
        g_centroid[l * 3 + 0] = g_sum[l * 3 + 0] * inv;
        g_centroid[l * 3 + 1] = g_sum[l * 3 + 1] * inv;
        g_centroid[l * 3 + 2] = g_sum[l * 3 + 2] * inv;
    }
    // zero accumulators for this pass
    for (int i = gt; i < L * CC; i += stride) g_shape_max[i] = 0.f;
    for (int i = gt; i < I * CC; i += stride) g_gkeys[i] = 0u;
    for (int i = gt; i < I; i += stride) g_cnt_i[i] = 0;
    // scatter
    if (gt < n) {
        int l = l2f[gt];
        int pos = atomicAdd(&g_cursor[l], 1);
        int slot = g_off[l] + pos;
        g_pids[slot] = gt;
        g_plocal[slot] = l;
    }
}

// ---------------- mma / ldmatrix helpers ----------------
__device__ __forceinline__ void mma16816(float* d, const unsigned* a, unsigned b0, unsigned b1) {
    asm volatile(
        "mma.sync.aligned.m16n8k16.row.col.f32.f16.f16.f32 "
        "{%0,%1,%2,%3}, {%4,%5,%6,%7}, {%8,%9}, {%0,%1,%2,%3};"
        : "+f"(d[0]), "+f"(d[1]), "+f"(d[2]), "+f"(d[3])
        : "r"(a[0]), "r"(a[1]), "r"(a[2]), "r"(a[3]), "r"(b0), "r"(b1));
}
__device__ __forceinline__ void ldm_x4(unsigned* r, uint32_t saddr) {
    asm volatile(
        "ldmatrix.sync.aligned.m8n8.x4.shared.b16 {%0,%1,%2,%3}, [%4];"
        : "=r"(r[0]), "=r"(r[1]), "=r"(r[2]), "=r"(r[3]) : "r"(saddr));
}

// ---------------- launch 4 (profiled): shape MLP ----------------
#define STRH 136
#define SH_SHAPE (128 * STRH * 2 * 2 + (384 + 128 + 128) * 4 + 128 * 4)

__global__ __launch_bounds__(256, 3) void k_shape(
    const float* __restrict__ xyz,
    const float* __restrict__ W1, const float* __restrict__ b1,
    const float* __restrict__ b2, int n)
{
    extern __shared__ char smraw[];
    __half* hA  = (__half*)smraw;                        // [128][STRH]
    __half* W2t = (__half*)(smraw + 128 * STRH * 2);     // [128][STRH]
    float*  outS = (float*)smraw;                        // reuse, [128][128]
    float*  ext = (float*)(smraw + 128 * STRH * 2 * 2);
    float*  W1s = ext;          // [dim][k]
    float*  b1s = ext + 384;
    float*  b2s = ext + 512;
    int*   lidS = (int*)(ext + 640);

    int tid = threadIdx.x;
    int tile0 = blockIdx.x * 128;

    for (int i = tid; i < 384; i += 256) W1s[i] = W1[i];
    if (tid < 128) { b1s[tid] = b1[tid]; b2s[tid] = b2[tid]; }
    __syncthreads();

    // layer1 (fp32 math, fp16 store) + W2t smem copy
    {
        int p = tid & 127, hid = tid >> 7;
        int row = tile0 + p;
        float cx = 0.f, cy = 0.f, cz = 0.f;
        int l = -1;
        bool valid = (row < n);
        if (valid) {
            int pid = g_pids[row];
            l = g_plocal[row];
            cx = xyz[pid * 3 + 0] - g_centroid[l * 3 + 0];
            cy = xyz[pid * 3 + 1] - g_centroid[l * 3 + 1];
            cz = xyz[pid * 3 + 2] - g_centroid[l * 3 + 2];
        }
        if (hid == 0) lidS[p] = l;
        int k0 = hid * 64;
        #pragma unroll 8
        for (int k = k0; k < k0 + 64; k += 2) {
            float h0 = fmaf(cx, W1s[k],   fmaf(cy, W1s[128 + k],   fmaf(cz, W1s[256 + k],   b1s[k])));
            float h1 = fmaf(cx, W1s[k+1], fmaf(cy, W1s[128 + k+1], fmaf(cz, W1s[256 + k+1], b1s[k+1])));
            h0 = valid ? fmaxf(h0, 0.f) : 0.f;
            h1 = valid ? fmaxf(h1, 0.f) : 0.f;
            *(__half2*)&hA[p * STRH + k] = __floats2half2_rn(h0, h1);
        }
        const unsigned* src = (const unsigned*)g_W2t;
        for (int i = tid; i < 8192; i += 256) {
            int c = i >> 6, k2 = (i & 63) << 1;
            *(unsigned*)&W2t[c * STRH + k2] = src[i];
        }
    }
    __syncthreads();

    // tensor-core GEMM: 128x128x128, warps 4(m) x 2(n), ldmatrix fragment loads
    int wid = tid >> 5, lane = tid & 31;
    int m0 = (wid >> 1) * 32, n0 = (wid & 1) * 64;
    int g = lane >> 2, t4 = (lane & 3) * 2;

    uint32_t hA_s  = (uint32_t)__cvta_generic_to_shared(hA);
    uint32_t W2t_s = (uint32_t)__cvta_generic_to_shared(W2t);
    uint32_t aAddr = hA_s  + ((m0 + (lane & 15)) * STRH + ((lane >> 4) << 3)) * 2;
    uint32_t bAddr = W2t_s + ((n0 + ((lane >> 4) << 3) + (lane & 7)) * STRH + (((lane >> 3) & 1) << 3)) * 2;

    float acc[2][8][4];
    #pragma unroll
    for (int a = 0; a < 2; a++)
        #pragma unroll
        for (int b_ = 0; b_ < 8; b_++)
            #pragma unroll
            for (int c = 0; c < 4; c++) acc[a][b_][c] = 0.f;

    #pragma unroll
    for (int kk = 0; kk < 128; kk += 16) {
        unsigned af[2][4];
        ldm_x4(af[0], aAddr + kk * 2);
        ldm_x4(af[1], aAddr + kk * 2 + 16 * STRH * 2);
        #pragma unroll
        for (int np = 0; np < 4; np++) {
            unsigned bf[4];
            ldm_x4(bf, bAddr + kk * 2 + np * 16 * STRH * 2);
            mma16816(acc[0][2*np],   af[0], bf[0], bf[1]);
            mma16816(acc[1][2*np],   af[1], bf[0], bf[1]);
            mma16816(acc[0][2*np+1], af[0], bf[2], bf[3]);
            mma16816(acc[1][2*np+1], af[1], bf[2], bf[3]);
        }
    }
    __syncthreads();   // done reading hA/W2t -> reuse as outS

    #pragma unroll
    for (int mt = 0; mt < 2; mt++) {
        #pragma unroll
        for (int nt = 0; nt < 8; nt++) {
            int r0 = m0 + mt * 16 + g;
            int c = n0 + nt * 8 + t4;
            float2 v0, v1;
            v0.x = fmaxf(acc[mt][nt][0] + b2s[c], 0.f);
            v0.y = fmaxf(acc[mt][nt][1] + b2s[c + 1], 0.f);
            v1.x = fmaxf(acc[mt][nt][2] + b2s[c], 0.f);
            v1.y = fmaxf(acc[mt][nt][3] + b2s[c + 1], 0.f);
            *(float2*)&outS[r0 * 128 + c] = v0;
            *(float2*)&outS[(r0 + 8) * 128 + c] = v1;
        }
    }
    __syncthreads();

    // segmented max over sorted locals: 256 threads, two row-halves per column.
    // Interior segments plain-store; half-boundary segments atomicMax (values >= 0).
    {
        int c = tid & 127, h = tid >> 7;
        int rs = h * 64, re = rs + 64;
        int cur = -2, s = rs;
        float m = 0.f;
        for (int r = rs; r < re; r++) {
            int l = lidS[r];
            float v = outS[r * 128 + c];
            if (l != cur) {
                if (cur >= 0) {
                    float* dst = &g_shape_max[(size_t)cur * CC + c];
                    if (s > rs) *dst = m;
                    else atomicMax((int*)dst, __float_as_int(m));
                }
                cur = l; m = v; s = r;
            } else m = fmaxf(m, v);
        }
        if (cur >= 0)
            atomicMax((int*)&g_shape_max[(size_t)cur * CC + c], __float_as_int(m));
    }
}

// ---------------- launch 5: fg_feat segmax + locals_feat + global key-max (+replay re-zero) ----------------
__global__ void k_featmax(const float* __restrict__ feat, const int* __restrict__ i2l, int L) {
    int gt = blockIdx.x * blockDim.x + threadIdx.x;
    // re-zero count/sum for the next graph replay (last readers were in k_csr)
    int stride = gridDim.x * blockDim.x;
    for (int i = gt; i < L; i += stride) g_cnt[i] = 0;
    for (int i = gt; i < 3 * L; i += stride) g_sum[i] = 0.f;

    int w = gt >> 5, lane = gt & 31;
    if (w >= L) return;
    int s = g_off[w], e = g_off[w + 1];
    float m0 = -CUDART_INF_F, m1 = m0, m2 = m0, m3 = m0;
    for (int p = s; p < e; p++) {
        const float* row = feat + (size_t)g_pids[p] * CC;
        m0 = fmaxf(m0, row[lane]);
        m1 = fmaxf(m1, row[lane + 32]);
        m2 = fmaxf(m2, row[lane + 64]);
        m3 = fmaxf(m3, row[lane + 96]);
    }
    if (e <= s) { m0 = m1 = m2 = m3 = 0.f; }
    size_t base = (size_t)w * CC;
    float v0 = m0 + g_shape_max[base + lane];
    float v1 = m1 + g_shape_max[base + lane + 32];
    float v2 = m2 + g_shape_max[base + lane + 64];
    float v3 = m3 + g_shape_max[base + lane + 96];
    g_locals_feat[base + lane]      = v0;
    g_locals_feat[base + lane + 32] = v1;
    g_locals_feat[base + lane + 64] = v2;
    g_locals_feat[base + lane + 96] = v3;
    int inst = i2l[w];
    size_t gb = (size_t)inst * CC;
    atomicMax(&g_gkeys[gb + lane],      fkey(v0));
    atomicMax(&g_gkeys[gb + lane + 32], fkey(v1));
    atomicMax(&g_gkeys[gb + lane + 64], fkey(v2));
    atomicMax(&g_gkeys[gb + lane + 96], fkey(v3));
    if (lane == 0) atomicAdd(&g_cnt_i[inst], 1);
}

// ---------------- launch 6: finalize globals + target centers ----------------
__global__ void k_gfin(const int* __restrict__ ils, int I) {
    int idx = blockIdx.x * blockDim.x + threadIdx.x;
    if (idx < I * CC) {
        int i = idx >> 7;
        g_globals[idx] = (g_cnt_i[i] > 0) ? funkey(g_gkeys[idx]) : 0.f;
    }
    if (idx < I * 3) {
        int i = idx / 3, d = idx % 3;
        g_gtlc[idx] = g_centroid[ils[i] * 3 + d];
    }
}

// ---------------- launch 7: locals MLP (mma.sync) + decoder ----------------
#define KF 262
#define KP 272
#define STRL 280
#define SH_MLP2 (2 * 128 * STRL * 2 + (128 + 128 + 1024 + 8) * 4 + 128 * 4)

__global__ __launch_bounds__(256) void k_mlp2(
    const float* __restrict__ b1, const float* __restrict__ b2,
    const float* __restrict__ Wd, const float* __restrict__ bd,
    const int* __restrict__ i2l,
    float* __restrict__ out_tf, float* __restrict__ out_fo, int L)
{
    extern __shared__ char smraw[];
    __half* A1 = (__half*)smraw;                         // [128][STRL]
    __half* B1 = (__half*)(smraw + 128 * STRL * 2);      // [128][STRL]
    float*  ext = (float*)(smraw + 2 * 128 * STRL * 2);
    float* b1L = ext;
    float* b2L = ext + 128;
    float* wdS = ext + 256;
    float* bdS = ext + 1280;
    int*   ilS = (int*)(ext + 1288);
    __half* hA2 = (__half*)smraw;                        // [128][STRH] (phase 2)
    __half* W2s = (__half*)(smraw + 128 * STRL * 2);     // [128][STRH] (phase 2)
    float*  foS = (float*)smraw;                         // [128][133] (phase 3)

    int tid = threadIdx.x;
    int block0 = blockIdx.x * 128;

    if (tid < 128) {
        b1L[tid] = b1[tid];
        b2L[tid] = b2[tid];
        int l = block0 + tid;
        ilS[tid] = (l < L) ? i2l[l] : 0;
    }
    for (int idx = tid; idx < 128 * 7; idx += 256)
        wdS[(idx / 7) * 8 + (idx % 7)] = Wd[idx];
    if (tid < 7) bdS[tid] = bd[tid];
    __syncthreads();

    for (int idx = tid; idx < 128 * KP; idx += 256) {
        int p = idx / KP, k = idx - p * KP;
        int l = block0 + p;
        float v = 0.f;
        if (l < L && k < KF) {
            int inst = ilS[p];
            if (k < 128)       v = g_locals_feat[(size_t)l * CC + k];
            else if (k < 256)  v = g_globals[(size_t)inst * CC + (k - 128)];
            else if (k < 259)  v = g_centroid[l * 3 + (k - 256)];
            else               v = g_gtlc[inst * 3 + (k - 259)];
        }
        A1[p * STRL + k] = __float2half(v);
    }
    {
        const unsigned* src = (const unsigned*)g_W1lt;
        for (int i = tid; i < 128 * (KP / 2); i += 256) {
            int h = i / (KP / 2), k2 = (i - h * (KP / 2)) << 1;
            *(unsigned*)&B1[h * STRL + k2] = src[i];
        }
    }
    __syncthreads();

    int wid = tid >> 5, lane = tid & 31;
    int m0 = (wid >> 1) * 32, n0 = (wid & 1) * 64;
    int g = lane >> 2, t4 = (lane & 3) * 2;

    uint32_t A1_s = (uint32_t)__cvta_generic_to_shared(A1);
    uint32_t B1_s = (uint32_t)__cvta_generic_to_shared(B1);
    uint32_t aOff = ((m0 + (lane & 15)) * STRL + ((lane >> 4) << 3)) * 2;
    uint32_t bOff = ((n0 + ((lane >> 4) << 3) + (lane & 7)) * STRL + (((lane >> 3) & 1) << 3)) * 2;

    float acc[2][8][4];
    #pragma unroll
    for (int a = 0; a < 2; a++)
        #pragma unroll
        for (int b_ = 0; b_ < 8; b_++)
            #pragma unroll
            for (int c = 0; c < 4; c++) acc[a][b_][c] = 0.f;

    #pragma unroll
    for (int kk = 0; kk < KP; kk += 16) {
        unsigned af[2][4];
        ldm_x4(af[0], A1_s + aOff + kk * 2);
        ldm_x4(af[1], A1_s + aOff + kk * 2 + 16 * STRL * 2);
        #pragma unroll
        for (int np = 0; np < 4; np++) {
            unsigned bf[4];
            ldm_x4(bf, B1_s + bOff + kk * 2 + np * 16 * STRL * 2);
            mma16816(acc[0][2*np],   af[0], bf[0], bf[1]);
            mma16816(acc[1][2*np],   af[1], bf[0], bf[1]);
            mma16816(acc[0][2*np+1], af[0], bf[2], bf[3]);
            mma16816(acc[1][2*np+1], af[1], bf[2], bf[3]);
        }
    }
    __syncthreads();

    #pragma unroll
    for (int mt = 0; mt < 2; mt++) {
        #pragma unroll
        for (int nt = 0; nt < 8; nt++) {
            int r0 = m0 + mt * 16 + g;
            int c = n0 + nt * 8 + t4;
            float h00 = fmaxf(acc[mt][nt][0] + b1L[c], 0.f);
            float h01 = fmaxf(acc[mt][nt][1] + b1L[c + 1], 0.f);
            float h10 = fmaxf(acc[mt][nt][2] + b1L[c], 0.f);
            float h11 = fmaxf(acc[mt][nt][3] + b1L[c + 1], 0.f);
            *(__half2*)&hA2[r0 * STRH + c] = __floats2half2_rn(h00, h01);
            *(__half2*)&hA2[(r0 + 8) * STRH + c] = __floats2half2_rn(h10, h11);
        }
    }
    {
        const unsigned* src = (const unsigned*)g_W2lt;
        for (int i = tid; i < 8192; i += 256) {
            int c = i >> 6, k2 = (i & 63) << 1;
            *(unsigned*)&W2s[c * STRH + k2] = src[i];
        }
    }
    __syncthreads();

    #pragma unroll
    for (int a = 0; a < 2; a++)
        #pragma unroll
        for (int b_ = 0; b_ < 8; b_++)
            #pragma unroll
            for (int c = 0; c < 4; c++) acc[a][b_][c] = 0.f;

    uint32_t hA2_s = (uint32_t)__cvta_generic_to_shared(hA2);
    uint32_t W2s_s = (uint32_t)__cvta_generic_to_shared(W2s);
    uint32_t aOff2 = ((m0 + (lane & 15)) * STRH + ((lane >> 4) << 3)) * 2;
    uint32_t bOff2 = ((n0 + ((lane >> 4) << 3) + (lane & 7)) * STRH + (((lane >> 3) & 1) << 3)) * 2;

    #pragma unroll
    for (int kk = 0; kk < 128; kk += 16) {
        unsigned af[2][4];
        ldm_x4(af[0], hA2_s + aOff2 + kk * 2);
        ldm_x4(af[1], hA2_s + aOff2 + kk * 2 + 16 * STRH * 2);
        #pragma unroll
        for (int np = 0; np < 4; np++) {
            unsigned bf[4];
            ldm_x4(bf, W2s_s + bOff2 + kk * 2 + np * 16 * STRH * 2);
            mma16816(acc[0][2*np],   af[0], bf[0], bf[1]);
            mma16816(acc[1][2*np],   af[1], bf[0], bf[1]);
            mma16816(acc[0][2*np+1], af[0], bf[2], bf[3]);
            mma16816(acc[1][2*np+1], af[1], bf[2], bf[3]);
        }
    }
    __syncthreads();

    #pragma unroll
    for (int mt = 0; mt < 2; mt++) {
        #pragma unroll
        for (int nt = 0; nt < 8; nt++) {
            int r0 = m0 + mt * 16 + g;
            int c = n0 + nt * 8 + t4;
            float v00 = fmaxf(acc[mt][nt][0] + b2L[c], 0.f);
            float v01 = fmaxf(acc[mt][nt][1] + b2L[c + 1], 0.f);
            float v10 = fmaxf(acc[mt][nt][2] + b2L[c], 0.f);
            float v11 = fmaxf(acc[mt][nt][3] + b2L[c + 1], 0.f);
            foS[r0 * 133 + c] = v00; foS[r0 * 133 + c + 1] = v01;
            foS[(r0 + 8) * 133 + c] = v10; foS[(r0 + 8) * 133 + c + 1] = v11;
            int l0 = block0 + r0, l1 = block0 + r0 + 8;
            if (l0 < L) { float2 s; s.x = v00; s.y = v01; *(float2*)&out_fo[(size_t)l0 * CC + c] = s; }
            if (l1 < L) { float2 s; s.x = v10; s.y = v11; *(float2*)&out_fo[(size_t)l1 * CC + c] = s; }
        }
    }
    __syncthreads();

    if (tid < 128) {
        int l = block0 + tid;
        if (l < L) {
            float s[7];
            #pragma unroll
            for (int j = 0; j < 7; j++) s[j] = bdS[j];
            for (int c = 0; c < 128; c++) {
                float f = foS[tid * 133 + c];
                #pragma unroll
                for (int j = 0; j < 7; j++) s[j] = fmaf(f, wdS[c * 8 + j], s[j]);
            }
            #pragma unroll
            for (int j = 0; j < 7; j++) out_tf[(size_t)l * 7 + j] = s[j];
        }
    }
}

// ---------------- launch ----------------
extern "C" void kernel_launch(void* const* d_in, const int* in_sizes, int n_in,
                              void* d_out, int out_size) {
    const float* xyz  = (const float*)d_in[0];
    const float* feat = (const float*)d_in[1];
    const float* W1s_ = (const float*)d_in[2];
    const float* b1s_ = (const float*)d_in[3];
    const float* W2s_ = (const float*)d_in[4];
    const float* b2s_ = (const float*)d_in[5];
    const float* W1l  = (const float*)d_in[6];
    const float* b1l  = (const float*)d_in[7];
    const float* W2l  = (const float*)d_in[8];
    const float* b2l  = (const float*)d_in[9];
    const float* Wd   = (const float*)d_in[10];
    const float* bd   = (const float*)d_in[11];
    const int*   l2f  = (const int*)d_in[12];
    const int*   i2l  = (const int*)d_in[13];
    const int*   ils  = (const int*)d_in[14];

    int n = in_sizes[0] / 3;
    int L = in_sizes[13];
    int I = in_sizes[14];

    float* out_tf = (float*)d_out;
    float* out_fo = (float*)d_out + (size_t)L * 7;

    cudaFuncSetAttribute(k_shape, cudaFuncAttributeMaxDynamicSharedMemorySize, SH_SHAPE);
    cudaFuncSetAttribute(k_mlp2,  cudaFuncAttributeMaxDynamicSharedMemorySize, SH_MLP2);

    // g_cnt/g_sum zero at first call (static init); re-zeroed in k_featmax each pass.
    k_count<<<(n + 255) / 256, 256>>>(xyz, l2f, n);                                       // 1
    k_scan<<<1, 1024>>>(L);                                                               // 2
    k_csr<<<(n + 255) / 256, 256>>>(l2f, W2s_, W1l, W2l, n, L, I);                        // 3
    k_shape<<<(n + 127) / 128, 256, SH_SHAPE>>>(xyz, W1s_, b1s_, b2s_, n);                // 4 <- profiled
    k_featmax<<<(L * 32 + 255) / 256, 256>>>(feat, i2l, L);                               // 5
    k_gfin<<<(I * CC + 255) / 256, 256>>>(ils, I);                                        // 6
    k_mlp2<<<(L + 127) / 128, 256, SH_MLP2>>>(b1l, b2l, Wd, bd, i2l, out_tf, out_fo, L);  // 7
}

// round 13
// speedup vs baseline: 1.2380x; 1.0633x over previous
#include <cuda_runtime.h>
#include <cuda_fp16.h>
#include <math_constants.h>
#include <stdint.h>

#define LMAX 100000
#define IMAX 10000
#define NMAX 1000000
#define CC 128

// ---------------- static device scratch (zero-initialized at module load) ----------------
__device__ int      g_cnt[LMAX];
__device__ float    g_sum[LMAX * 3];
__device__ float    g_centroid[LMAX * 3];
__device__ int      g_off[LMAX + 1];
__device__ int      g_cursor[LMAX];
__device__ int      g_pids[NMAX];
__device__ int      g_plocal[NMAX];
__device__ float    g_shape_max[(size_t)LMAX * CC];
__device__ float    g_locals_feat[(size_t)LMAX * CC];
__device__ int      g_cnt_i[IMAX];
__device__ unsigned g_gkeys[(size_t)IMAX * CC];
__device__ float    g_gtlc[IMAX * 3];
__device__ float    g_globals[(size_t)IMAX * CC];
__device__ __half   g_W2t[128 * 128];     // W2_shape^T fp16: [c][k] linear
__device__ __half   g_W1lt[128 * 272];    // W1_loc^T fp16, K padded 262->272: [h][k]
__device__ __half   g_W2lt[128 * 128];    // W2_loc^T fp16: [c][k]

// order-preserving float->uint key for atomicMax on signed floats.
__device__ __forceinline__ unsigned fkey(float f) {
    unsigned b = __float_as_uint(f);
    return (b & 0x80000000u) ? ~b : (b | 0x80000000u);
}
__device__ __forceinline__ float funkey(unsigned k) {
    return (k & 0x80000000u) ? __uint_as_float(k & 0x7fffffffu) : __uint_as_float(~k);
}

// ---------------- launch 1: centroid count + sum ----------------
__global__ void k_count(const float* __restrict__ xyz, const int* __restrict__ l2f, int n) {
    int i = blockIdx.x * blockDim.x + threadIdx.x;
    if (i >= n) return;
    int l = l2f[i];
    atomicAdd(&g_cnt[l], 1);
    atomicAdd(&g_sum[l * 3 + 0], xyz[i * 3 + 0]);
    atomicAdd(&g_sum[l * 3 + 1], xyz[i * 3 + 1]);
    atomicAdd(&g_sum[l * 3 + 2], xyz[i * 3 + 2]);
}

// ---------------- launch 2: exclusive scan of g_cnt + cursor zero (single block) ----------------
__global__ void k_scan(int L) {
    __shared__ int wsum[32];
    int tid = threadIdx.x;                 // 1024 threads
    for (int l = tid; l < L; l += 1024) g_cursor[l] = 0;

    int chunk = (L + 1023) >> 10;
    int s = tid * chunk;
    int e = s + chunk; if (e > L) e = L;
    if (s > L) s = L;
    int sum = 0;
    for (int i = s; i < e; i++) sum += g_cnt[i];

    int lane = tid & 31, w = tid >> 5;
    int v = sum;
    #pragma unroll
    for (int o = 1; o < 32; o <<= 1) {
        int t = __shfl_up_sync(0xffffffffu, v, o);
        if (lane >= o) v += t;
    }
    if (lane == 31) wsum[w] = v;
    __syncthreads();
    if (w == 0) {
        int x = wsum[lane];
        #pragma unroll
        for (int o = 1; o < 32; o <<= 1) {
            int t = __shfl_up_sync(0xffffffffu, x, o);
            if (lane >= o) x += t;
        }
        wsum[lane] = x;
    }
    __syncthreads();
    int excl = v - sum + (w > 0 ? wsum[w - 1] : 0);
    int run = excl;
    for (int i = s; i < e; i++) { int c = g_cnt[i]; g_off[i] = run; run += c; }
    if (tid == 1023) g_off[L] = run;
}

// ---------------- launch 3: CSR scatter + centroid + weight prep + zero (wide grid) ----------------
__global__ void k_csr(const int* __restrict__ l2f,
                      const float* __restrict__ W2s_, const float* __restrict__ W1l,
                      const float* __restrict__ W2l,
                      int n, int L, int I) {
    int gt = blockIdx.x * blockDim.x + threadIdx.x;
    int stride = gridDim.x * blockDim.x;

    for (int i = gt; i < 16384; i += stride) {
        int c = i >> 7, k = i & 127;
        g_W2t[i]  = __float2half(W2s_[k * 128 + c]);
        g_W2lt[i] = __float2half(W2l[k * 128 + c]);
    }
    for (int i = gt; i < 128 * 272; i += stride) {
        int h = i / 272, k = i - h * 272;
        g_W1lt[i] = (k < 262) ? __float2half(W1l[k * 128 + h]) : __half(0.f);
    }
    for (int l = gt; l < L; l += stride) {
        float inv = 1.f / fmaxf((float)g_cnt[l], 1.f);
        g_centroid[l * 3 + 0] = g_sum[l * 3 + 0] * inv;
        g_centroid[l * 3 + 1] = g_sum[l * 3 + 1] * inv;
        g_centroid[l * 3 + 2] = g_sum[l * 3 + 2] * inv;
    }
    for (int i = gt; i < L * CC; i += stride) g_shape_max[i] = 0.f;
    for (int i = gt; i < I * CC; i += stride) g_gkeys[i] = 0u;
    for (int i = gt; i < I; i += stride) g_cnt_i[i] = 0;
    if (gt < n) {
        int l = l2f[gt];
        int pos = atomicAdd(&g_cursor[l], 1);
        int slot = g_off[l] + pos;
        g_pids[slot] = gt;
        g_plocal[slot] = l;
    }
}

// ---------------- mma / ldmatrix helpers ----------------
__device__ __forceinline__ void mma16816(float* d, const unsigned* a, unsigned b0, unsigned b1) {
    asm volatile(
        "mma.sync.aligned.m16n8k16.row.col.f32.f16.f16.f32 "
        "{%0,%1,%2,%3}, {%4,%5,%6,%7}, {%8,%9}, {%0,%1,%2,%3};"
        : "+f"(d[0]), "+f"(d[1]), "+f"(d[2]), "+f"(d[3])
        : "r"(a[0]), "r"(a[1]), "r"(a[2]), "r"(a[3]), "r"(b0), "r"(b1));
}
__device__ __forceinline__ void ldm_x4(unsigned* r, uint32_t saddr) {
    asm volatile(
        "ldmatrix.sync.aligned.m8n8.x4.shared.b16 {%0,%1,%2,%3}, [%4];"
        : "=r"(r[0]), "=r"(r[1]), "=r"(r[2]), "=r"(r[3]) : "r"(saddr));
}

// ---------------- launch 4 (profiled): shape MLP ----------------
// smem: hA half[128][136] | W2t half[128][136]   (69632 B, overlaid by outS f32[128][136])
//       cS float4[128] (2048) | b2s f32[128] (512) | lidS int[128] (512)
#define STRH 136
#define OSTR 136
#define SH_SHAPE (69632 + 2048 + 512 + 512)

__global__ __launch_bounds__(256, 3) void k_shape(
    const float* __restrict__ xyz,
    const float* __restrict__ W1, const float* __restrict__ b1,
    const float* __restrict__ b2, int n)
{
    extern __shared__ char smraw[];
    __half* hA  = (__half*)smraw;                        // [128][STRH]
    __half* W2t = (__half*)(smraw + 128 * STRH * 2);     // [128][STRH]
    float*  outS = (float*)smraw;                        // overlay, [128][OSTR]
    float*  cS  = (float*)(smraw + 69632);               // float4 per point
    float*  b2s = cS + 512;
    int*   lidS = (int*)(b2s + 128);

    int tid = threadIdx.x;
    int tile0 = blockIdx.x * 128;

    // phase A: coords gather (tid<128) || W2t smem copy (tid>=128)
    if (tid < 128) {
        int p = tid;
        int row = tile0 + p;
        float cx = 0.f, cy = 0.f, cz = 0.f;
        int l = -1;
        if (row < n) {
            int pid = g_pids[row];
            l = g_plocal[row];
            cx = xyz[pid * 3 + 0] - g_centroid[l * 3 + 0];
            cy = xyz[pid * 3 + 1] - g_centroid[l * 3 + 1];
            cz = xyz[pid * 3 + 2] - g_centroid[l * 3 + 2];
        }
        float4 c4; c4.x = cx; c4.y = cy; c4.z = cz; c4.w = 0.f;
        *(float4*)&cS[p * 4] = c4;
        lidS[p] = l;
        b2s[p] = b2[p];
    } else {
        int t = tid - 128;
        const unsigned* src = (const unsigned*)g_W2t;
        for (int i = t; i < 8192; i += 128) {
            int c = i >> 6, k2 = (i & 63) << 1;
            *(unsigned*)&W2t[c * STRH + k2] = src[i];
        }
    }
    __syncthreads();

    // phase B: layer1, lanes on k (conflict-free stores), weights in registers.
    // Invalid rows (row>=n) produce garbage h; never consumed (GEMM rows discarded,
    // segmax skips lid=-1 segments).
    {
        int k = (tid & 63) * 2;       // this thread's two k's
        int p0 = (tid >> 6) * 32;     // 32-point group
        float w0x = W1[k],       w1x = W1[k + 1];
        float w0y = W1[128 + k], w1y = W1[129 + k];
        float w0z = W1[256 + k], w1z = W1[257 + k];
        float bb0 = b1[k],       bb1 = b1[k + 1];
        #pragma unroll 8
        for (int pp = 0; pp < 32; pp++) {
            int p = p0 + pp;
            float4 c4 = *(const float4*)&cS[p * 4];
            float h0 = fmaf(c4.x, w0x, fmaf(c4.y, w0y, fmaf(c4.z, w0z, bb0)));
            float h1 = fmaf(c4.x, w1x, fmaf(c4.y, w1y, fmaf(c4.z, w1z, bb1)));
            h0 = fmaxf(h0, 0.f);
            h1 = fmaxf(h1, 0.f);
            *(__half2*)&hA[p * STRH + k] = __floats2half2_rn(h0, h1);
        }
    }
    __syncthreads();

    // tensor-core GEMM: 128x128x128, warps 4(m) x 2(n), ldmatrix fragment loads
    int wid = tid >> 5, lane = tid & 31;
    int m0 = (wid >> 1) * 32, n0 = (wid & 1) * 64;
    int g = lane >> 2, t4 = (lane & 3) * 2;

    uint32_t hA_s  = (uint32_t)__cvta_generic_to_shared(hA);
    uint32_t W2t_s = (uint32_t)__cvta_generic_to_shared(W2t);
    uint32_t aAddr = hA_s  + ((m0 + (lane & 15)) * STRH + ((lane >> 4) << 3)) * 2;
    uint32_t bAddr = W2t_s + ((n0 + ((lane >> 4) << 3) + (lane & 7)) * STRH + (((lane >> 3) & 1) << 3)) * 2;

    float acc[2][8][4];
    #pragma unroll
    for (int a = 0; a < 2; a++)
        #pragma unroll
        for (int b_ = 0; b_ < 8; b_++)
            #pragma unroll
            for (int c = 0; c < 4; c++) acc[a][b_][c] = 0.f;

    #pragma unroll
    for (int kk = 0; kk < 128; kk += 16) {
        unsigned af[2][4];
        ldm_x4(af[0], aAddr + kk * 2);
        ldm_x4(af[1], aAddr + kk * 2 + 16 * STRH * 2);
        #pragma unroll
        for (int np = 0; np < 4; np++) {
            unsigned bf[4];
            ldm_x4(bf, bAddr + kk * 2 + np * 16 * STRH * 2);
            mma16816(acc[0][2*np],   af[0], bf[0], bf[1]);
            mma16816(acc[1][2*np],   af[1], bf[0], bf[1]);
            mma16816(acc[0][2*np+1], af[0], bf[2], bf[3]);
            mma16816(acc[1][2*np+1], af[1], bf[2], bf[3]);
        }
    }
    __syncthreads();   // done reading hA/W2t -> reuse as outS

    #pragma unroll
    for (int mt = 0; mt < 2; mt++) {
        #pragma unroll
        for (int nt = 0; nt < 8; nt++) {
            int r0 = m0 + mt * 16 + g;
            int c = n0 + nt * 8 + t4;
            float2 v0, v1;
            v0.x = fmaxf(acc[mt][nt][0] + b2s[c], 0.f);
            v0.y = fmaxf(acc[mt][nt][1] + b2s[c + 1], 0.f);
            v1.x = fmaxf(acc[mt][nt][2] + b2s[c], 0.f);
            v1.y = fmaxf(acc[mt][nt][3] + b2s[c + 1], 0.f);
            *(float2*)&outS[r0 * OSTR + c] = v0;
            *(float2*)&outS[(r0 + 8) * OSTR + c] = v1;
        }
    }
    __syncthreads();

    // segmented max over sorted locals: 256 threads, two row-halves per column.
    {
        int c = tid & 127, h = tid >> 7;
        int rs = h * 64, re = rs + 64;
        int cur = -2, s = rs;
        float m = 0.f;
        for (int r = rs; r < re; r++) {
            int l = lidS[r];
            float v = outS[r * OSTR + c];
            if (l != cur) {
                if (cur >= 0) {
                    float* dst = &g_shape_max[(size_t)cur * CC + c];
                    if (s > rs) *dst = m;
                    else atomicMax((int*)dst, __float_as_int(m));
                }
                cur = l; m = v; s = r;
            } else m = fmaxf(m, v);
        }
        if (cur >= 0)
            atomicMax((int*)&g_shape_max[(size_t)cur * CC + c], __float_as_int(m));
    }
}

// ---------------- launch 5: fg_feat segmax + locals_feat + global key-max (+replay re-zero) ----------------
__global__ void k_featmax(const float* __restrict__ feat, const int* __restrict__ i2l, int L) {
    int gt = blockIdx.x * blockDim.x + threadIdx.x;
    int stride = gridDim.x * blockDim.x;
    for (int i = gt; i < L; i += stride) g_cnt[i] = 0;
    for (int i = gt; i < 3 * L; i += stride) g_sum[i] = 0.f;

    int w = gt >> 5, lane = gt & 31;
    if (w >= L) return;
    int s = g_off[w], e = g_off[w + 1];
    float m0 = -CUDART_INF_F, m1 = m0, m2 = m0, m3 = m0;
    for (int p = s; p < e; p++) {
        const float* row = feat + (size_t)g_pids[p] * CC;
        m0 = fmaxf(m0, row[lane]);
        m1 = fmaxf(m1, row[lane + 32]);
        m2 = fmaxf(m2, row[lane + 64]);
        m3 = fmaxf(m3, row[lane + 96]);
    }
    if (e <= s) { m0 = m1 = m2 = m3 = 0.f; }
    size_t base = (size_t)w * CC;
    float v0 = m0 + g_shape_max[base + lane];
    float v1 = m1 + g_shape_max[base + lane + 32];
    float v2 = m2 + g_shape_max[base + lane + 64];
    float v3 = m3 + g_shape_max[base + lane + 96];
    g_locals_feat[base + lane]      = v0;
    g_locals_feat[base + lane + 32] = v1;
    g_locals_feat[base + lane + 64] = v2;
    g_locals_feat[base + lane + 96] = v3;
    int inst = i2l[w];
    size_t gb = (size_t)inst * CC;
    atomicMax(&g_gkeys[gb + lane],      fkey(v0));
    atomicMax(&g_gkeys[gb + lane + 32], fkey(v1));
    atomicMax(&g_gkeys[gb + lane + 64], fkey(v2));
    atomicMax(&g_gkeys[gb + lane + 96], fkey(v3));
    if (lane == 0) atomicAdd(&g_cnt_i[inst], 1);
}

// ---------------- launch 6: finalize globals + target centers ----------------
__global__ void k_gfin(const int* __restrict__ ils, int I) {
    int idx = blockIdx.x * blockDim.x + threadIdx.x;
    if (idx < I * CC) {
        int i = idx >> 7;
        g_globals[idx] = (g_cnt_i[i] > 0) ? funkey(g_gkeys[idx]) : 0.f;
    }
    if (idx < I * 3) {
        int i = idx / 3, d = idx % 3;
        g_gtlc[idx] = g_centroid[ils[i] * 3 + d];
    }
}

// ---------------- launch 7: locals MLP (mma.sync) + decoder ----------------
#define KF 262
#define KP 272
#define STRL 280
#define SH_MLP2 (2 * 128 * STRL * 2 + (128 + 128 + 1024 + 8) * 4 + 128 * 4)

__global__ __launch_bounds__(256) void k_mlp2(
    const float* __restrict__ b1, const float* __restrict__ b2,
    const float* __restrict__ Wd, const float* __restrict__ bd,
    const int* __restrict__ i2l,
    float* __restrict__ out_tf, float* __restrict__ out_fo, int L)
{
    extern __shared__ char smraw[];
    __half* A1 = (__half*)smraw;                         // [128][STRL]
    __half* B1 = (__half*)(smraw + 128 * STRL * 2);      // [128][STRL]
    float*  ext = (float*)(smraw + 2 * 128 * STRL * 2);
    float* b1L = ext;
    float* b2L = ext + 128;
    float* wdS = ext + 256;
    float* bdS = ext + 1280;
    int*   ilS = (int*)(ext + 1288);
    __half* hA2 = (__half*)smraw;                        // [128][STRH] (phase 2)
    __half* W2s = (__half*)(smraw + 128 * STRL * 2);     // [128][STRH] (phase 2)
    float*  foS = (float*)smraw;                         // [128][133] (phase 3)

    int tid = threadIdx.x;
    int block0 = blockIdx.x * 128;

    if (tid < 128) {
        b1L[tid] = b1[tid];
        b2L[tid] = b2[tid];
        int l = block0 + tid;
        ilS[tid] = (l < L) ? i2l[l] : 0;
    }
    for (int idx = tid; idx < 128 * 7; idx += 256)
        wdS[(idx / 7) * 8 + (idx % 7)] = Wd[idx];
    if (tid < 7) bdS[tid] = bd[tid];
    __syncthreads();

    for (int idx = tid; idx < 128 * KP; idx += 256) {
        int p = idx / KP, k = idx - p * KP;
        int l = block0 + p;
        float v = 0.f;
        if (l < L && k < KF) {
            int inst = ilS[p];
            if (k < 128)       v = g_locals_feat[(size_t)l * CC + k];
            else if (k < 256)  v = g_globals[(size_t)inst * CC + (k - 128)];
            else if (k < 259)  v = g_centroid[l * 3 + (k - 256)];
            else               v = g_gtlc[inst * 3 + (k - 259)];
        }
        A1[p * STRL + k] = __float2half(v);
    }
    {
        const unsigned* src = (const unsigned*)g_W1lt;
        for (int i = tid; i < 128 * (KP / 2); i += 256) {
            int h = i / (KP / 2), k2 = (i - h * (KP / 2)) << 1;
            *(unsigned*)&B1[h * STRL + k2] = src[i];
        }
    }
    __syncthreads();

    int wid = tid >> 5, lane = tid & 31;
    int m0 = (wid >> 1) * 32, n0 = (wid & 1) * 64;
    int g = lane >> 2, t4 = (lane & 3) * 2;

    uint32_t A1_s = (uint32_t)__cvta_generic_to_shared(A1);
    uint32_t B1_s = (uint32_t)__cvta_generic_to_shared(B1);
    uint32_t aOff = ((m0 + (lane & 15)) * STRL + ((lane >> 4) << 3)) * 2;
    uint32_t bOff = ((n0 + ((lane >> 4) << 3) + (lane & 7)) * STRL + (((lane >> 3) & 1) << 3)) * 2;

    float acc[2][8][4];
    #pragma unroll
    for (int a = 0; a < 2; a++)
        #pragma unroll
        for (int b_ = 0; b_ < 8; b_++)
            #pragma unroll
            for (int c = 0; c < 4; c++) acc[a][b_][c] = 0.f;

    #pragma unroll
    for (int kk = 0; kk < KP; kk += 16) {
        unsigned af[2][4];
        ldm_x4(af[0], A1_s + aOff + kk * 2);
        ldm_x4(af[1], A1_s + aOff + kk * 2 + 16 * STRL * 2);
        #pragma unroll
        for (int np = 0; np < 4; np++) {
            unsigned bf[4];
            ldm_x4(bf, B1_s + bOff + kk * 2 + np * 16 * STRL * 2);
            mma16816(acc[0][2*np],   af[0], bf[0], bf[1]);
            mma16816(acc[1][2*np],   af[1], bf[0], bf[1]);
            mma16816(acc[0][2*np+1], af[0], bf[2], bf[3]);
            mma16816(acc[1][2*np+1], af[1], bf[2], bf[3]);
        }
    }
    __syncthreads();

    #pragma unroll
    for (int mt = 0; mt < 2; mt++) {
        #pragma unroll
        for (int nt = 0; nt < 8; nt++) {
            int r0 = m0 + mt * 16 + g;
            int c = n0 + nt * 8 + t4;
            float h00 = fmaxf(acc[mt][nt][0] + b1L[c], 0.f);
            float h01 = fmaxf(acc[mt][nt][1] + b1L[c + 1], 0.f);
            float h10 = fmaxf(acc[mt][nt][2] + b1L[c], 0.f);
            float h11 = fmaxf(acc[mt][nt][3] + b1L[c + 1], 0.f);
            *(__half2*)&hA2[r0 * STRH + c] = __floats2half2_rn(h00, h01);
            *(__half2*)&hA2[(r0 + 8) * STRH + c] = __floats2half2_rn(h10, h11);
        }
    }
    {
        const unsigned* src = (const unsigned*)g_W2lt;
        for (int i = tid; i < 8192; i += 256) {
            int c = i >> 6, k2 = (i & 63) << 1;
            *(unsigned*)&W2s[c * STRH + k2] = src[i];
        }
    }
    __syncthreads();

    #pragma unroll
    for (int a = 0; a < 2; a++)
        #pragma unroll
        for (int b_ = 0; b_ < 8; b_++)
            #pragma unroll
            for (int c = 0; c < 4; c++) acc[a][b_][c] = 0.f;

    uint32_t hA2_s = (uint32_t)__cvta_generic_to_shared(hA2);
    uint32_t W2s_s = (uint32_t)__cvta_generic_to_shared(W2s);
    uint32_t aOff2 = ((m0 + (lane & 15)) * STRH + ((lane >> 4) << 3)) * 2;
    uint32_t bOff2 = ((n0 + ((lane >> 4) << 3) + (lane & 7)) * STRH + (((lane >> 3) & 1) << 3)) * 2;

    #pragma unroll
    for (int kk = 0; kk < 128; kk += 16) {
        unsigned af[2][4];
        ldm_x4(af[0], hA2_s + aOff2 + kk * 2);
        ldm_x4(af[1], hA2_s + aOff2 + kk * 2 + 16 * STRH * 2);
        #pragma unroll
        for (int np = 0; np < 4; np++) {
            unsigned bf[4];
            ldm_x4(bf, W2s_s + bOff2 + kk * 2 + np * 16 * STRH * 2);
            mma16816(acc[0][2*np],   af[0], bf[0], bf[1]);
            mma16816(acc[1][2*np],   af[1], bf[0], bf[1]);
            mma16816(acc[0][2*np+1], af[0], bf[2], bf[3]);
            mma16816(acc[1][2*np+1], af[1], bf[2], bf[3]);
        }
    }
    __syncthreads();

    #pragma unroll
    for (int mt = 0; mt < 2; mt++) {
        #pragma unroll
        for (int nt = 0; nt < 8; nt++) {
            int r0 = m0 + mt * 16 + g;
            int c = n0 + nt * 8 + t4;
            float v00 = fmaxf(acc[mt][nt][0] + b2L[c], 0.f);
            float v01 = fmaxf(acc[mt][nt][1] + b2L[c + 1], 0.f);
            float v10 = fmaxf(acc[mt][nt][2] + b2L[c], 0.f);
            float v11 = fmaxf(acc[mt][nt][3] + b2L[c + 1], 0.f);
            foS[r0 * 133 + c] = v00; foS[r0 * 133 + c + 1] = v01;
            foS[(r0 + 8) * 133 + c] = v10; foS[(r0 + 8) * 133 + c + 1] = v11;
            int l0 = block0 + r0, l1 = block0 + r0 + 8;
            if (l0 < L) { float2 s; s.x = v00; s.y = v01; *(float2*)&out_fo[(size_t)l0 * CC + c] = s; }
            if (l1 < L) { float2 s; s.x = v10; s.y = v11; *(float2*)&out_fo[(size_t)l1 * CC + c] = s; }
        }
    }
    __syncthreads();

    if (tid < 128) {
        int l = block0 + tid;
        if (l < L) {
            float s[7];
            #pragma unroll
            for (int j = 0; j < 7; j++) s[j] = bdS[j];
            for (int c = 0; c < 128; c++) {
                float f = foS[tid * 133 + c];
                #pragma unroll
                for (int j = 0; j < 7; j++) s[j] = fmaf(f, wdS[c * 8 + j], s[j]);
            }
            #pragma unroll
            for (int j = 0; j < 7; j++) out_tf[(size_t)l * 7 + j] = s[j];
        }
    }
}

// ---------------- launch ----------------
extern "C" void kernel_launch(void* const* d_in, const int* in_sizes, int n_in,
                              void* d_out, int out_size) {
    const float* xyz  = (const float*)d_in[0];
    const float* feat = (const float*)d_in[1];
    const float* W1s_ = (const float*)d_in[2];
    const float* b1s_ = (const float*)d_in[3];
    const float* W2s_ = (const float*)d_in[4];
    const float* b2s_ = (const float*)d_in[5];
    const float* W1l  = (const float*)d_in[6];
    const float* b1l  = (const float*)d_in[7];
    const float* W2l  = (const float*)d_in[8];
    const float* b2l  = (const float*)d_in[9];
    const float* Wd   = (const float*)d_in[10];
    const float* bd   = (const float*)d_in[11];
    const int*   l2f  = (const int*)d_in[12];
    const int*   i2l  = (const int*)d_in[13];
    const int*   ils  = (const int*)d_in[14];

    int n = in_sizes[0] / 3;
    int L = in_sizes[13];
    int I = in_sizes[14];

    float* out_tf = (float*)d_out;
    float* out_fo = (float*)d_out + (size_t)L * 7;

    cudaFuncSetAttribute(k_shape, cudaFuncAttributeMaxDynamicSharedMemorySize, SH_SHAPE);
    cudaFuncSetAttribute(k_mlp2,  cudaFuncAttributeMaxDynamicSharedMemorySize, SH_MLP2);

    // g_cnt/g_sum zero at first call (static init); re-zeroed in k_featmax each pass.
    k_count<<<(n + 255) / 256, 256>>>(xyz, l2f, n);                                       // 1
    k_scan<<<1, 1024>>>(L);                                                               // 2
    k_csr<<<(n + 255) / 256, 256>>>(l2f, W2s_, W1l, W2l, n, L, I);                        // 3
    k_shape<<<(n + 127) / 128, 256, SH_SHAPE>>>(xyz, W1s_, b1s_, b2s_, n);                // 4 <- profiled
    k_featmax<<<(L * 32 + 255) / 256, 256>>>(feat, i2l, L);                               // 5
    k_gfin<<<(I * CC + 255) / 256, 256>>>(ils, I);                                        // 6
    k_mlp2<<<(L + 127) / 128, 256, SH_MLP2>>>(b1l, b2l, Wd, bd, i2l, out_tf, out_fo, L);  // 7
}

// round 15
// speedup vs baseline: 1.4589x; 1.1784x over previous
#include <cuda_runtime.h>
#include <cuda_fp16.h>
#include <math_constants.h>
#include <stdint.h>

#define LMAX 100000
#define IMAX 10000
#define NMAX 1000000
#define CC 128

// ---------------- static device scratch (zero-initialized at module load) ----------------
__device__ int      g_cnt[LMAX];
__device__ float    g_sum[LMAX * 3];
__device__ float    g_centroid[LMAX * 3];
__device__ int      g_off[LMAX + 1];
__device__ int      g_cursor[LMAX];
__device__ int      g_pids[NMAX];
__device__ int      g_plocal[NMAX];
__device__ float    g_shape_max[(size_t)LMAX * CC];
__device__ float    g_locals_feat[(size_t)LMAX * CC];
__device__ int      g_cnt_i[IMAX];
__device__ unsigned g_gkeys[(size_t)IMAX * CC];
__device__ float    g_gtlc[IMAX * 3];
__device__ float    g_globals[(size_t)IMAX * CC];
__device__ __half   g_W2t[128 * 128];     // W2_shape^T fp16: [c][k] linear
__device__ __half   g_W1lt[128 * 272];    // W1_loc^T fp16, K padded 262->272: [h][k]
__device__ __half   g_W2lt[128 * 128];    // W2_loc^T fp16: [c][k]

// order-preserving float->uint key for atomicMax on signed floats.
__device__ __forceinline__ unsigned fkey(float f) {
    unsigned b = __float_as_uint(f);
    return (b & 0x80000000u) ? ~b : (b | 0x80000000u);
}
__device__ __forceinline__ float funkey(unsigned k) {
    return (k & 0x80000000u) ? __uint_as_float(k & 0x7fffffffu) : __uint_as_float(~k);
}

// ---------------- launch 1: centroid count + sum ----------------
__global__ void k_count(const float* __restrict__ xyz, const int* __restrict__ l2f, int n) {
    int i = blockIdx.x * blockDim.x + threadIdx.x;
    if (i >= n) return;
    int l = l2f[i];
    atomicAdd(&g_cnt[l], 1);
    atomicAdd(&g_sum[l * 3 + 0], xyz[i * 3 + 0]);
    atomicAdd(&g_sum[l * 3 + 1], xyz[i * 3 + 1]);
    atomicAdd(&g_sum[l * 3 + 2], xyz[i * 3 + 2]);
}

// ---------------- launch 2: exclusive scan of g_cnt + cursor zero (single block) ----------------
__global__ void k_scan(int L) {
    __shared__ int wsum[32];
    int tid = threadIdx.x;                 // 1024 threads
    for (int l = tid; l < L; l += 1024) g_cursor[l] = 0;

    int chunk = (L + 1023) >> 10;
    int s = tid * chunk;
    int e = s + chunk; if (e > L) e = L;
    if (s > L) s = L;
    int sum = 0;
    for (int i = s; i < e; i++) sum += g_cnt[i];

    int lane = tid & 31, w = tid >> 5;
    int v = sum;
    #pragma unroll
    for (int o = 1; o < 32; o <<= 1) {
        int t = __shfl_up_sync(0xffffffffu, v, o);
        if (lane >= o) v += t;
    }
    if (lane == 31) wsum[w] = v;
    __syncthreads();
    if (w == 0) {
        int x = wsum[lane];
        #pragma unroll
        for (int o = 1; o < 32; o <<= 1) {
            int t = __shfl_up_sync(0xffffffffu, x, o);
            if (lane >= o) x += t;
        }
        wsum[lane] = x;
    }
    __syncthreads();
    int excl = v - sum + (w > 0 ? wsum[w - 1] : 0);
    int run = excl;
    for (int i = s; i < e; i++) { int c = g_cnt[i]; g_off[i] = run; run += c; }
    if (tid == 1023) g_off[L] = run;
}

// ---------------- launch 3: CSR scatter + centroid + weight prep + zero (wide grid) ----------------
__global__ void k_csr(const int* __restrict__ l2f,
                      const float* __restrict__ W2s_, const float* __restrict__ W1l,
                      const float* __restrict__ W2l,
                      int n, int L, int I) {
    int gt = blockIdx.x * blockDim.x + threadIdx.x;
    int stride = gridDim.x * blockDim.x;

    for (int i = gt; i < 16384; i += stride) {
        int c = i >> 7, k = i & 127;
        g_W2t[i]  = __float2half(W2s_[k * 128 + c]);
        g_W2lt[i] = __float2half(W2l[k * 128 + c]);
    }
    for (int i = gt; i < 128 * 272; i += stride) {
        int h = i / 272, k = i - h * 272;
        g_W1lt[i] = (k < 262) ? __float2half(W1l[k * 128 + h]) : __half(0.f);
    }
    for (int l = gt; l < L; l += stride) {
        float inv = 1.f / fmaxf((float)g_cnt[l], 1.f);
        g_centroid[l * 3 + 0] = g_sum[l * 3 + 0] * inv;
        g_centroid[l * 3 + 1] = g_sum[l * 3 + 1] * inv;
        g_centroid[l * 3 + 2] = g_sum[l * 3 + 2] * inv;
    }
    for (int i = gt; i < L * CC; i += stride) g_shape_max[i] = 0.f;
    for (int i = gt; i < I * CC; i += stride) g_gkeys[i] = 0u;
    for (int i = gt; i < I; i += stride) g_cnt_i[i] = 0;
    if (gt < n) {
        int l = l2f[gt];
        int pos = atomicAdd(&g_cursor[l], 1);
        int slot = g_off[l] + pos;
        g_pids[slot] = gt;
        g_plocal[slot] = l;
    }
}

// ---------------- mma / ldmatrix helpers ----------------
__device__ __forceinline__ void mma16816(float* d, const unsigned* a, unsigned b0, unsigned b1) {
    asm volatile(
        "mma.sync.aligned.m16n8k16.row.col.f32.f16.f16.f32 "
        "{%0,%1,%2,%3}, {%4,%5,%6,%7}, {%8,%9}, {%0,%1,%2,%3};"
        : "+f"(d[0]), "+f"(d[1]), "+f"(d[2]), "+f"(d[3])
        : "r"(a[0]), "r"(a[1]), "r"(a[2]), "r"(a[3]), "r"(b0), "r"(b1));
}
__device__ __forceinline__ void ldm_x4(unsigned* r, uint32_t saddr) {
    asm volatile(
        "ldmatrix.sync.aligned.m8n8.x4.shared.b16 {%0,%1,%2,%3}, [%4];"
        : "=r"(r[0]), "=r"(r[1]), "=r"(r[2]), "=r"(r[3]) : "r"(saddr));
}

// ---------------- launch 4 (profiled): shape MLP ----------------
// smem: hA half[128][136] | W2t half[128][136]   (69632 B, overlaid by outS f32[128][136])
//       cS float4[128] (2048) | b2s f32[128] (512) | lidS int[128] (512)
#define STRH 136
#define OSTR 136
#define SH_SHAPE (69632 + 2048 + 512 + 512)

__global__ __launch_bounds__(256, 3) void k_shape(
    const float* __restrict__ xyz,
    const float* __restrict__ W1, const float* __restrict__ b1,
    const float* __restrict__ b2, int n)
{
    extern __shared__ char smraw[];
    __half* hA  = (__half*)smraw;                        // [128][STRH]
    __half* W2t = (__half*)(smraw + 128 * STRH * 2);     // [128][STRH]
    float*  outS = (float*)smraw;                        // overlay, [128][OSTR]
    float*  cS  = (float*)(smraw + 69632);               // float4 per point
    float*  b2s = cS + 512;
    int*   lidS = (int*)(b2s + 128);

    int tid = threadIdx.x;
    int tile0 = blockIdx.x * 128;

    // phase A: coords gather (tid<128) || W2t smem copy (tid>=128)
    if (tid < 128) {
        int p = tid;
        int row = tile0 + p;
        float cx = 0.f, cy = 0.f, cz = 0.f;
        int l = -1;
        if (row < n) {
            int pid = g_pids[row];
            l = g_plocal[row];
            cx = xyz[pid * 3 + 0] - g_centroid[l * 3 + 0];
            cy = xyz[pid * 3 + 1] - g_centroid[l * 3 + 1];
            cz = xyz[pid * 3 + 2] - g_centroid[l * 3 + 2];
        }
        float4 c4; c4.x = cx; c4.y = cy; c4.z = cz; c4.w = 0.f;
        *(float4*)&cS[p * 4] = c4;
        lidS[p] = l;
        b2s[p] = b2[p];
    } else {
        int t = tid - 128;
        const unsigned* src = (const unsigned*)g_W2t;
        for (int i = t; i < 8192; i += 128) {
            int c = i >> 6, k2 = (i & 63) << 1;
            *(unsigned*)&W2t[c * STRH + k2] = src[i];
        }
    }
    __syncthreads();

    // phase B: layer1, lanes on k (conflict-free stores), weights in registers.
    {
        int k = (tid & 63) * 2;       // this thread's two k's
        int p0 = (tid >> 6) * 32;     // 32-point group
        float w0x = W1[k],       w1x = W1[k + 1];
        float w0y = W1[128 + k], w1y = W1[129 + k];
        float w0z = W1[256 + k], w1z = W1[257 + k];
        float bb0 = b1[k],       bb1 = b1[k + 1];
        #pragma unroll 8
        for (int pp = 0; pp < 32; pp++) {
            int p = p0 + pp;
            float4 c4 = *(const float4*)&cS[p * 4];
            float h0 = fmaf(c4.x, w0x, fmaf(c4.y, w0y, fmaf(c4.z, w0z, bb0)));
            float h1 = fmaf(c4.x, w1x, fmaf(c4.y, w1y, fmaf(c4.z, w1z, bb1)));
            h0 = fmaxf(h0, 0.f);
            h1 = fmaxf(h1, 0.f);
            *(__half2*)&hA[p * STRH + k] = __floats2half2_rn(h0, h1);
        }
    }
    __syncthreads();

    // tensor-core GEMM: 128x128x128, warps 4(m) x 2(n), ldmatrix fragment loads
    int wid = tid >> 5, lane = tid & 31;
    int m0 = (wid >> 1) * 32, n0 = (wid & 1) * 64;
    int g = lane >> 2, t4 = (lane & 3) * 2;

    uint32_t hA_s  = (uint32_t)__cvta_generic_to_shared(hA);
    uint32_t W2t_s = (uint32_t)__cvta_generic_to_shared(W2t);
    uint32_t aAddr = hA_s  + ((m0 + (lane & 15)) * STRH + ((lane >> 4) << 3)) * 2;
    uint32_t bAddr = W2t_s + ((n0 + ((lane >> 4) << 3) + (lane & 7)) * STRH + (((lane >> 3) & 1) << 3)) * 2;

    float acc[2][8][4];
    #pragma unroll
    for (int a = 0; a < 2; a++)
        #pragma unroll
        for (int b_ = 0; b_ < 8; b_++)
            #pragma unroll
            for (int c = 0; c < 4; c++) acc[a][b_][c] = 0.f;

    #pragma unroll
    for (int kk = 0; kk < 128; kk += 16) {
        unsigned af[2][4];
        ldm_x4(af[0], aAddr + kk * 2);
        ldm_x4(af[1], aAddr + kk * 2 + 16 * STRH * 2);
        #pragma unroll
        for (int np = 0; np < 4; np++) {
            unsigned bf[4];
            ldm_x4(bf, bAddr + kk * 2 + np * 16 * STRH * 2);
            mma16816(acc[0][2*np],   af[0], bf[0], bf[1]);
            mma16816(acc[1][2*np],   af[1], bf[0], bf[1]);
            mma16816(acc[0][2*np+1], af[0], bf[2], bf[3]);
            mma16816(acc[1][2*np+1], af[1], bf[2], bf[3]);
        }
    }
    __syncthreads();   // done reading hA/W2t -> reuse as outS

    #pragma unroll
    for (int mt = 0; mt < 2; mt++) {
        #pragma unroll
        for (int nt = 0; nt < 8; nt++) {
            int r0 = m0 + mt * 16 + g;
            int c = n0 + nt * 8 + t4;
            float2 v0, v1;
            v0.x = fmaxf(acc[mt][nt][0] + b2s[c], 0.f);
            v0.y = fmaxf(acc[mt][nt][1] + b2s[c + 1], 0.f);
            v1.x = fmaxf(acc[mt][nt][2] + b2s[c], 0.f);
            v1.y = fmaxf(acc[mt][nt][3] + b2s[c + 1], 0.f);
            *(float2*)&outS[r0 * OSTR + c] = v0;
            *(float2*)&outS[(r0 + 8) * OSTR + c] = v1;
        }
    }
    __syncthreads();

    // segmented max over sorted locals: 256 threads, two row-halves per column.
    {
        int c = tid & 127, h = tid >> 7;
        int rs = h * 64, re = rs + 64;
        int cur = -2, s = rs;
        float m = 0.f;
        for (int r = rs; r < re; r++) {
            int l = lidS[r];
            float v = outS[r * OSTR + c];
            if (l != cur) {
                if (cur >= 0) {
                    float* dst = &g_shape_max[(size_t)cur * CC + c];
                    if (s > rs) *dst = m;
                    else atomicMax((int*)dst, __float_as_int(m));
                }
                cur = l; m = v; s = r;
            } else m = fmaxf(m, v);
        }
        if (cur >= 0)
            atomicMax((int*)&g_shape_max[(size_t)cur * CC + c], __float_as_int(m));
    }
}

// ---------------- launch 5: fg_feat segmax + locals_feat + global key-max (+replay re-zero) ----------------
__global__ void k_featmax(const float* __restrict__ feat, const int* __restrict__ i2l, int L) {
    int gt = blockIdx.x * blockDim.x + threadIdx.x;
    int stride = gridDim.x * blockDim.x;
    for (int i = gt; i < L; i += stride) g_cnt[i] = 0;
    for (int i = gt; i < 3 * L; i += stride) g_sum[i] = 0.f;

    int w = gt >> 5, lane = gt & 31;
    if (w >= L) return;
    int s = g_off[w], e = g_off[w + 1];
    float m0 = -CUDART_INF_F, m1 = m0, m2 = m0, m3 = m0;
    for (int p = s; p < e; p++) {
        const float* row = feat + (size_t)g_pids[p] * CC;
        m0 = fmaxf(m0, row[lane]);
        m1 = fmaxf(m1, row[lane + 32]);
        m2 = fmaxf(m2, row[lane + 64]);
        m3 = fmaxf(m3, row[lane + 96]);
    }
    if (e <= s) { m0 = m1 = m2 = m3 = 0.f; }
    size_t base = (size_t)w * CC;
    float v0 = m0 + g_shape_max[base + lane];
    float v1 = m1 + g_shape_max[base + lane + 32];
    float v2 = m2 + g_shape_max[base + lane + 64];
    float v3 = m3 + g_shape_max[base + lane + 96];
    g_locals_feat[base + lane]      = v0;
    g_locals_feat[base + lane + 32] = v1;
    g_locals_feat[base + lane + 64] = v2;
    g_locals_feat[base + lane + 96] = v3;
    int inst = i2l[w];
    size_t gb = (size_t)inst * CC;
    atomicMax(&g_gkeys[gb + lane],      fkey(v0));
    atomicMax(&g_gkeys[gb + lane + 32], fkey(v1));
    atomicMax(&g_gkeys[gb + lane + 64], fkey(v2));
    atomicMax(&g_gkeys[gb + lane + 96], fkey(v3));
    if (lane == 0) atomicAdd(&g_cnt_i[inst], 1);
}

// ---------------- launch 6: finalize globals + target centers ----------------
__global__ void k_gfin(const int* __restrict__ ils, int I) {
    int idx = blockIdx.x * blockDim.x + threadIdx.x;
    if (idx < I * CC) {
        int i = idx >> 7;
        g_globals[idx] = (g_cnt_i[i] > 0) ? funkey(g_gkeys[idx]) : 0.f;
    }
    if (idx < I * 3) {
        int i = idx / 3, d = idx % 3;
        g_gtlc[idx] = g_centroid[ils[i] * 3 + d];
    }
}

// ---------------- launch 7: locals MLP (mma.sync, B streamed in 2 k-chunks) ----------------
// smem: A1 half[128][280] (71680) | B1c half[128][152] (38912) | b1L,b2L f32[128] + ilS int[128]
// overlays: hA2 half[128][136] on A1, W2s half[128][136] on B1c, foS f32[128][133] on A1
#define KF 262
#define KP 272
#define STRL 280
#define STRB 152
#define KCH0 144
#define SH_MLP2 (71680 + 38912 + 1536)

__global__ __launch_bounds__(256, 2) void k_mlp2(
    const float* __restrict__ b1, const float* __restrict__ b2,
    const float* __restrict__ Wd, const float* __restrict__ bd,
    const int* __restrict__ i2l,
    float* __restrict__ out_tf, float* __restrict__ out_fo, int L)
{
    extern __shared__ char smraw[];
    __half* A1  = (__half*)smraw;                        // [128][STRL]
    __half* B1c = (__half*)(smraw + 71680);              // [128][STRB]
    float*  ext = (float*)(smraw + 71680 + 38912);
    float* b1L = ext;            // 128
    float* b2L = ext + 128;      // 128
    int*   ilS = (int*)(ext + 256);
    __half* hA2 = (__half*)smraw;                        // [128][136] (phase 2)
    __half* W2s = B1c;                                   // [128][136] (phase 2)
    float*  foS = (float*)smraw;                         // [128][133] (phase 3)

    int tid = threadIdx.x;
    int block0 = blockIdx.x * 128;

    if (tid < 128) {
        b1L[tid] = b1[tid];
        b2L[tid] = b2[tid];
        int l = block0 + tid;
        ilS[tid] = (l < L) ? i2l[l] : 0;
    }
    __syncthreads();

    // assemble feat fp16 into A1[p][k]; load B chunk 0 (k 0..143)
    for (int idx = tid; idx < 128 * KP; idx += 256) {
        int p = idx / KP, k = idx - p * KP;
        int l = block0 + p;
        float v = 0.f;
        if (l < L && k < KF) {
            int inst = ilS[p];
            if (k < 128)       v = g_locals_feat[(size_t)l * CC + k];
            else if (k < 256)  v = g_globals[(size_t)inst * CC + (k - 128)];
            else if (k < 259)  v = g_centroid[l * 3 + (k - 256)];
            else               v = g_gtlc[inst * 3 + (k - 259)];
        }
        A1[p * STRL + k] = __float2half(v);
    }
    {
        const unsigned* src = (const unsigned*)g_W1lt;   // [h][272] halves = [h][136] uints
        for (int i = tid; i < 128 * 72; i += 256) {
            int h = i / 72, j = i - h * 72;
            *(unsigned*)&B1c[h * STRB + j * 2] = src[h * 136 + j];
        }
    }
    __syncthreads();

    int wid = tid >> 5, lane = tid & 31;
    int m0 = (wid >> 1) * 32, n0 = (wid & 1) * 64;
    int g = lane >> 2, t4 = (lane & 3) * 2;

    uint32_t A1_s  = (uint32_t)__cvta_generic_to_shared(A1);
    uint32_t B1c_s = (uint32_t)__cvta_generic_to_shared(B1c);
    uint32_t aOff = ((m0 + (lane & 15)) * STRL + ((lane >> 4) << 3)) * 2;
    uint32_t bOff = ((n0 + ((lane >> 4) << 3) + (lane & 7)) * STRB + (((lane >> 3) & 1) << 3)) * 2;

    float acc[2][8][4];
    #pragma unroll
    for (int a = 0; a < 2; a++)
        #pragma unroll
        for (int b_ = 0; b_ < 8; b_++)
            #pragma unroll
            for (int c = 0; c < 4; c++) acc[a][b_][c] = 0.f;

    // GEMM1 stage 0: k 0..143
    #pragma unroll
    for (int kk = 0; kk < KCH0; kk += 16) {
        unsigned af[2][4];
        ldm_x4(af[0], A1_s + aOff + kk * 2);
        ldm_x4(af[1], A1_s + aOff + kk * 2 + 16 * STRL * 2);
        #pragma unroll
        for (int np = 0; np < 4; np++) {
            unsigned bf[4];
            ldm_x4(bf, B1c_s + bOff + kk * 2 + np * 16 * STRB * 2);
            mma16816(acc[0][2*np],   af[0], bf[0], bf[1]);
            mma16816(acc[1][2*np],   af[1], bf[0], bf[1]);
            mma16816(acc[0][2*np+1], af[0], bf[2], bf[3]);
            mma16816(acc[1][2*np+1], af[1], bf[2], bf[3]);
        }
    }
    __syncthreads();
    // load B chunk 1 (k 144..271 -> 64 uints per row)
    {
        const unsigned* src = (const unsigned*)g_W1lt;
        for (int i = tid; i < 128 * 64; i += 256) {
            int h = i >> 6, j = i & 63;
            *(unsigned*)&B1c[h * STRB + j * 2] = src[h * 136 + 72 + j];
        }
    }
    __syncthreads();
    // GEMM1 stage 1: k 144..271
    #pragma unroll
    for (int kk = 0; kk < KP - KCH0; kk += 16) {
        unsigned af[2][4];
        ldm_x4(af[0], A1_s + aOff + (KCH0 + kk) * 2);
        ldm_x4(af[1], A1_s + aOff + (KCH0 + kk) * 2 + 16 * STRL * 2);
        #pragma unroll
        for (int np = 0; np < 4; np++) {
            unsigned bf[4];
            ldm_x4(bf, B1c_s + bOff + kk * 2 + np * 16 * STRB * 2);
            mma16816(acc[0][2*np],   af[0], bf[0], bf[1]);
            mma16816(acc[1][2*np],   af[1], bf[0], bf[1]);
            mma16816(acc[0][2*np+1], af[0], bf[2], bf[3]);
            mma16816(acc[1][2*np+1], af[1], bf[2], bf[3]);
        }
    }
    __syncthreads();  // A1/B1c reads done -> overlays

    // epilogue 1: relu(acc + b1) -> hA2 fp16; copy W2lt into W2s
    #define STRH2 136
    #pragma unroll
    for (int mt = 0; mt < 2; mt++) {
        #pragma unroll
        for (int nt = 0; nt < 8; nt++) {
            int r0 = m0 + mt * 16 + g;
            int c = n0 + nt * 8 + t4;
            float h00 = fmaxf(acc[mt][nt][0] + b1L[c], 0.f);
            float h01 = fmaxf(acc[mt][nt][1] + b1L[c + 1], 0.f);
            float h10 = fmaxf(acc[mt][nt][2] + b1L[c], 0.f);
            float h11 = fmaxf(acc[mt][nt][3] + b1L[c + 1], 0.f);
            *(__half2*)&hA2[r0 * STRH2 + c] = __floats2half2_rn(h00, h01);
            *(__half2*)&hA2[(r0 + 8) * STRH2 + c] = __floats2half2_rn(h10, h11);
        }
    }
    {
        const unsigned* src = (const unsigned*)g_W2lt;
        for (int i = tid; i < 8192; i += 256) {
            int c = i >> 6, k2 = (i & 63) << 1;
            *(unsigned*)&W2s[c * STRH2 + k2] = src[i];
        }
    }
    __syncthreads();

    // GEMM2: K=128
    #pragma unroll
    for (int a = 0; a < 2; a++)
        #pragma unroll
        for (int b_ = 0; b_ < 8; b_++)
            #pragma unroll
            for (int c = 0; c < 4; c++) acc[a][b_][c] = 0.f;

    uint32_t hA2_s = (uint32_t)__cvta_generic_to_shared(hA2);
    uint32_t W2s_s = (uint32_t)__cvta_generic_to_shared(W2s);
    uint32_t aOff2 = ((m0 + (lane & 15)) * STRH2 + ((lane >> 4) << 3)) * 2;
    uint32_t bOff2 = ((n0 + ((lane >> 4) << 3) + (lane & 7)) * STRH2 + (((lane >> 3) & 1) << 3)) * 2;

    #pragma unroll
    for (int kk = 0; kk < 128; kk += 16) {
        unsigned af[2][4];
        ldm_x4(af[0], hA2_s + aOff2 + kk * 2);
        ldm_x4(af[1], hA2_s + aOff2 + kk * 2 + 16 * STRH2 * 2);
        #pragma unroll
        for (int np = 0; np < 4; np++) {
            unsigned bf[4];
            ldm_x4(bf, W2s_s + bOff2 + kk * 2 + np * 16 * STRH2 * 2);
            mma16816(acc[0][2*np],   af[0], bf[0], bf[1]);
            mma16816(acc[1][2*np],   af[1], bf[0], bf[1]);
            mma16816(acc[0][2*np+1], af[0], bf[2], bf[3]);
            mma16816(acc[1][2*np+1], af[1], bf[2], bf[3]);
        }
    }
    __syncthreads();  // hA2/W2s reads done -> foS

    // epilogue 2: relu(acc + b2) -> out_fo + foS
    #pragma unroll
    for (int mt = 0; mt < 2; mt++) {
        #pragma unroll
        for (int nt = 0; nt < 8; nt++) {
            int r0 = m0 + mt * 16 + g;
            int c = n0 + nt * 8 + t4;
            float v00 = fmaxf(acc[mt][nt][0] + b2L[c], 0.f);
            float v01 = fmaxf(acc[mt][nt][1] + b2L[c + 1], 0.f);
            float v10 = fmaxf(acc[mt][nt][2] + b2L[c], 0.f);
            float v11 = fmaxf(acc[mt][nt][3] + b2L[c + 1], 0.f);
            foS[r0 * 133 + c] = v00; foS[r0 * 133 + c + 1] = v01;
            foS[(r0 + 8) * 133 + c] = v10; foS[(r0 + 8) * 133 + c + 1] = v11;
            int l0 = block0 + r0, l1 = block0 + r0 + 8;
            if (l0 < L) { float2 s; s.x = v00; s.y = v01; *(float2*)&out_fo[(size_t)l0 * CC + c] = s; }
            if (l1 < L) { float2 s; s.x = v10; s.y = v11; *(float2*)&out_fo[(size_t)l1 * CC + c] = s; }
        }
    }
    __syncthreads();

    // decoder: Wd/bd from gmem (L2-hot)
    if (tid < 128) {
        int l = block0 + tid;
        if (l < L) {
            float s[7];
            #pragma unroll
            for (int j = 0; j < 7; j++) s[j] = bd[j];
            for (int c = 0; c < 128; c++) {
                float f = foS[tid * 133 + c];
                #pragma unroll
                for (int j = 0; j < 7; j++) s[j] = fmaf(f, Wd[c * 7 + j], s[j]);
            }
            #pragma unroll
            for (int j = 0; j < 7; j++) out_tf[(size_t)l * 7 + j] = s[j];
        }
    }
}

// ---------------- launch ----------------
extern "C" void kernel_launch(void* const* d_in, const int* in_sizes, int n_in,
                              void* d_out, int out_size) {
    const float* xyz  = (const float*)d_in[0];
    const float* feat = (const float*)d_in[1];
    const float* W1s_ = (const float*)d_in[2];
    const float* b1s_ = (const float*)d_in[3];
    const float* W2s_ = (const float*)d_in[4];
    const float* b2s_ = (const float*)d_in[5];
    const float* W1l  = (const float*)d_in[6];
    const float* b1l  = (const float*)d_in[7];
    const float* W2l  = (const float*)d_in[8];
    const float* b2l  = (const float*)d_in[9];
    const float* Wd   = (const float*)d_in[10];
    const float* bd   = (const float*)d_in[11];
    const int*   l2f  = (const int*)d_in[12];
    const int*   i2l  = (const int*)d_in[13];
    const int*   ils  = (const int*)d_in[14];

    int n = in_sizes[0] / 3;
    int L = in_sizes[13];
    int I = in_sizes[14];

    float* out_tf = (float*)d_out;
    float* out_fo = (float*)d_out + (size_t)L * 7;

    cudaFuncSetAttribute(k_shape, cudaFuncAttributeMaxDynamicSharedMemorySize, SH_SHAPE);
    cudaFuncSetAttribute(k_mlp2,  cudaFuncAttributeMaxDynamicSharedMemorySize, SH_MLP2);

    // g_cnt/g_sum zero at first call (static init); re-zeroed in k_featmax each pass.
    k_count<<<(n + 255) / 256, 256>>>(xyz, l2f, n);                                       // 1
    k_scan<<<1, 1024>>>(L);                                                               // 2
    k_csr<<<(n + 255) / 256, 256>>>(l2f, W2s_, W1l, W2l, n, L, I);                        // 3
    k_shape<<<(n + 127) / 128, 256, SH_SHAPE>>>(xyz, W1s_, b1s_, b2s_, n);                // 4 <- profiled
    k_featmax<<<(L * 32 + 255) / 256, 256>>>(feat, i2l, L);                               // 5
    k_gfin<<<(I * CC + 255) / 256, 256>>>(ils, I);                                        // 6
    k_mlp2<<<(L + 127) / 128, 256, SH_MLP2>>>(b1l, b2l, Wd, bd, i2l, out_tf, out_fo, L);  // 7
}

// round 16
// speedup vs baseline: 1.5348x; 1.0521x over previous
#include <cuda_runtime.h>
#include <cuda_fp16.h>
#include <math_constants.h>
#include <stdint.h>

#define LMAX 100000
#define IMAX 10000
#define NMAX 1000000
#define CC 128

// ---------------- static device scratch (zero-initialized at module load) ----------------
__device__ int      g_cnt[LMAX];
__device__ float    g_sum[LMAX * 3];
__device__ float    g_centroid[LMAX * 3];
__device__ int      g_off[LMAX + 1];
__device__ int      g_cursor[LMAX];
__device__ int      g_pids[NMAX];
__device__ int      g_plocal[NMAX];
__device__ float    g_shape_max[(size_t)LMAX * CC];
__device__ float    g_locals_feat[(size_t)LMAX * CC];
__device__ int      g_cnt_i[IMAX];
__device__ unsigned g_gkeys[(size_t)IMAX * CC];
__device__ float    g_gtlc[IMAX * 3];
__device__ float    g_globals[(size_t)IMAX * CC];
__device__ __half   g_W2t[128 * 128];     // W2_shape^T fp16: [c][k] linear
__device__ __half   g_W1lt[128 * 272];    // W1_loc^T fp16, K padded 262->272: [h][k]
__device__ __half   g_W2lt[128 * 128];    // W2_loc^T fp16: [c][k]

// order-preserving float->uint key for atomicMax on signed floats.
__device__ __forceinline__ unsigned fkey(float f) {
    unsigned b = __float_as_uint(f);
    return (b & 0x80000000u) ? ~b : (b | 0x80000000u);
}
__device__ __forceinline__ float funkey(unsigned k) {
    return (k & 0x80000000u) ? __uint_as_float(k & 0x7fffffffu) : __uint_as_float(~k);
}

// ---------------- launch 1: centroid count + sum ----------------
__global__ void k_count(const float* __restrict__ xyz, const int* __restrict__ l2f, int n) {
    int i = blockIdx.x * blockDim.x + threadIdx.x;
    if (i >= n) return;
    int l = l2f[i];
    atomicAdd(&g_cnt[l], 1);
    atomicAdd(&g_sum[l * 3 + 0], xyz[i * 3 + 0]);
    atomicAdd(&g_sum[l * 3 + 1], xyz[i * 3 + 1]);
    atomicAdd(&g_sum[l * 3 + 2], xyz[i * 3 + 2]);
}

// ---------------- launch 2: exclusive scan of g_cnt + cursor zero (single block) ----------------
__global__ void k_scan(int L) {
    __shared__ int wsum[32];
    int tid = threadIdx.x;                 // 1024 threads
    for (int l = tid; l < L; l += 1024) g_cursor[l] = 0;

    int chunk = (L + 1023) >> 10;
    int s = tid * chunk;
    int e = s + chunk; if (e > L) e = L;
    if (s > L) s = L;
    int sum = 0;
    for (int i = s; i < e; i++) sum += g_cnt[i];

    int lane = tid & 31, w = tid >> 5;
    int v = sum;
    #pragma unroll
    for (int o = 1; o < 32; o <<= 1) {
        int t = __shfl_up_sync(0xffffffffu, v, o);
        if (lane >= o) v += t;
    }
    if (lane == 31) wsum[w] = v;
    __syncthreads();
    if (w == 0) {
        int x = wsum[lane];
        #pragma unroll
        for (int o = 1; o < 32; o <<= 1) {
            int t = __shfl_up_sync(0xffffffffu, x, o);
            if (lane >= o) x += t;
        }
        wsum[lane] = x;
    }
    __syncthreads();
    int excl = v - sum + (w > 0 ? wsum[w - 1] : 0);
    int run = excl;
    for (int i = s; i < e; i++) { int c = g_cnt[i]; g_off[i] = run; run += c; }
    if (tid == 1023) g_off[L] = run;
}

// ---------------- launch 3: CSR scatter + centroid + weight prep + zero (wide grid) ----------------
__global__ void k_csr(const int* __restrict__ l2f,
                      const float* __restrict__ W2s_, const float* __restrict__ W1l,
                      const float* __restrict__ W2l,
                      int n, int L, int I) {
    int gt = blockIdx.x * blockDim.x + threadIdx.x;
    int stride = gridDim.x * blockDim.x;

    for (int i = gt; i < 16384; i += stride) {
        int c = i >> 7, k = i & 127;
        g_W2t[i]  = __float2half(W2s_[k * 128 + c]);
        g_W2lt[i] = __float2half(W2l[k * 128 + c]);
    }
    for (int i = gt; i < 128 * 272; i += stride) {
        int h = i / 272, k = i - h * 272;
        g_W1lt[i] = (k < 262) ? __float2half(W1l[k * 128 + h]) : __half(0.f);
    }
    for (int l = gt; l < L; l += stride) {
        float inv = 1.f / fmaxf((float)g_cnt[l], 1.f);
        g_centroid[l * 3 + 0] = g_sum[l * 3 + 0] * inv;
        g_centroid[l * 3 + 1] = g_sum[l * 3 + 1] * inv;
        g_centroid[l * 3 + 2] = g_sum[l * 3 + 2] * inv;
    }
    for (int i = gt; i < L * CC; i += stride) g_shape_max[i] = 0.f;
    for (int i = gt; i < I * CC; i += stride) g_gkeys[i] = 0u;
    for (int i = gt; i < I; i += stride) g_cnt_i[i] = 0;
    if (gt < n) {
        int l = l2f[gt];
        int pos = atomicAdd(&g_cursor[l], 1);
        int slot = g_off[l] + pos;
        g_pids[slot] = gt;
        g_plocal[slot] = l;
    }
}

// ---------------- mma / ldmatrix helpers ----------------
__device__ __forceinline__ void mma16816(float* d, const unsigned* a, unsigned b0, unsigned b1) {
    asm volatile(
        "mma.sync.aligned.m16n8k16.row.col.f32.f16.f16.f32 "
        "{%0,%1,%2,%3}, {%4,%5,%6,%7}, {%8,%9}, {%0,%1,%2,%3};"
        : "+f"(d[0]), "+f"(d[1]), "+f"(d[2]), "+f"(d[3])
        : "r"(a[0]), "r"(a[1]), "r"(a[2]), "r"(a[3]), "r"(b0), "r"(b1));
}
__device__ __forceinline__ void ldm_x4(unsigned* r, uint32_t saddr) {
    asm volatile(
        "ldmatrix.sync.aligned.m8n8.x4.shared.b16 {%0,%1,%2,%3}, [%4];"
        : "=r"(r[0]), "=r"(r[1]), "=r"(r[2]), "=r"(r[3]) : "r"(saddr));
}

// ---------------- launch 4 (profiled): shape MLP ----------------
// smem: hA half[128][136] | W2t half[128][136]   (69632 B, overlaid by outS f32[128][136])
//       cS float4[128] (2048) | b2s f32[128] (512) | lidS int[128] (512)
#define STRH 136
#define OSTR 136
#define SH_SHAPE (69632 + 2048 + 512 + 512)

__global__ __launch_bounds__(256, 3) void k_shape(
    const float* __restrict__ xyz,
    const float* __restrict__ W1, const float* __restrict__ b1,
    const float* __restrict__ b2, int n)
{
    extern __shared__ char smraw[];
    __half* hA  = (__half*)smraw;                        // [128][STRH]
    __half* W2t = (__half*)(smraw + 128 * STRH * 2);     // [128][STRH]
    float*  outS = (float*)smraw;                        // overlay, [128][OSTR]
    float*  cS  = (float*)(smraw + 69632);               // float4 per point
    float*  b2s = cS + 512;
    int*   lidS = (int*)(b2s + 128);

    int tid = threadIdx.x;
    int tile0 = blockIdx.x * 128;

    // phase A: coords gather (tid<128) || W2t smem copy (tid>=128)
    if (tid < 128) {
        int p = tid;
        int row = tile0 + p;
        float cx = 0.f, cy = 0.f, cz = 0.f;
        int l = -1;
        if (row < n) {
            int pid = g_pids[row];
            l = g_plocal[row];
            cx = xyz[pid * 3 + 0] - g_centroid[l * 3 + 0];
            cy = xyz[pid * 3 + 1] - g_centroid[l * 3 + 1];
            cz = xyz[pid * 3 + 2] - g_centroid[l * 3 + 2];
        }
        float4 c4; c4.x = cx; c4.y = cy; c4.z = cz; c4.w = 0.f;
        *(float4*)&cS[p * 4] = c4;
        lidS[p] = l;
        b2s[p] = b2[p];
    } else {
        int t = tid - 128;
        const unsigned* src = (const unsigned*)g_W2t;
        for (int i = t; i < 8192; i += 128) {
            int c = i >> 6, k2 = (i & 63) << 1;
            *(unsigned*)&W2t[c * STRH + k2] = src[i];
        }
    }
    __syncthreads();

    // phase B: layer1, lanes on k (conflict-free stores), weights in registers.
    {
        int k = (tid & 63) * 2;       // this thread's two k's
        int p0 = (tid >> 6) * 32;     // 32-point group
        float w0x = W1[k],       w1x = W1[k + 1];
        float w0y = W1[128 + k], w1y = W1[129 + k];
        float w0z = W1[256 + k], w1z = W1[257 + k];
        float bb0 = b1[k],       bb1 = b1[k + 1];
        #pragma unroll 8
        for (int pp = 0; pp < 32; pp++) {
            int p = p0 + pp;
            float4 c4 = *(const float4*)&cS[p * 4];
            float h0 = fmaf(c4.x, w0x, fmaf(c4.y, w0y, fmaf(c4.z, w0z, bb0)));
            float h1 = fmaf(c4.x, w1x, fmaf(c4.y, w1y, fmaf(c4.z, w1z, bb1)));
            h0 = fmaxf(h0, 0.f);
            h1 = fmaxf(h1, 0.f);
            *(__half2*)&hA[p * STRH + k] = __floats2half2_rn(h0, h1);
        }
    }
    __syncthreads();

    // tensor-core GEMM: 128x128x128, warps 4(m) x 2(n), ldmatrix fragment loads
    int wid = tid >> 5, lane = tid & 31;
    int m0 = (wid >> 1) * 32, n0 = (wid & 1) * 64;
    int g = lane >> 2, t4 = (lane & 3) * 2;

    uint32_t hA_s  = (uint32_t)__cvta_generic_to_shared(hA);
    uint32_t W2t_s = (uint32_t)__cvta_generic_to_shared(W2t);
    uint32_t aAddr = hA_s  + ((m0 + (lane & 15)) * STRH + ((lane >> 4) << 3)) * 2;
    uint32_t bAddr = W2t_s + ((n0 + ((lane >> 4) << 3) + (lane & 7)) * STRH + (((lane >> 3) & 1) << 3)) * 2;

    float acc[2][8][4];
    #pragma unroll
    for (int a = 0; a < 2; a++)
        #pragma unroll
        for (int b_ = 0; b_ < 8; b_++)
            #pragma unroll
            for (int c = 0; c < 4; c++) acc[a][b_][c] = 0.f;

    #pragma unroll
    for (int kk = 0; kk < 128; kk += 16) {
        unsigned af[2][4];
        ldm_x4(af[0], aAddr + kk * 2);
        ldm_x4(af[1], aAddr + kk * 2 + 16 * STRH * 2);
        #pragma unroll
        for (int np = 0; np < 4; np++) {
            unsigned bf[4];
            ldm_x4(bf, bAddr + kk * 2 + np * 16 * STRH * 2);
            mma16816(acc[0][2*np],   af[0], bf[0], bf[1]);
            mma16816(acc[1][2*np],   af[1], bf[0], bf[1]);
            mma16816(acc[0][2*np+1], af[0], bf[2], bf[3]);
            mma16816(acc[1][2*np+1], af[1], bf[2], bf[3]);
        }
    }
    __syncthreads();   // done reading hA/W2t -> reuse as outS

    #pragma unroll
    for (int mt = 0; mt < 2; mt++) {
        #pragma unroll
        for (int nt = 0; nt < 8; nt++) {
            int r0 = m0 + mt * 16 + g;
            int c = n0 + nt * 8 + t4;
            float2 v0, v1;
            v0.x = fmaxf(acc[mt][nt][0] + b2s[c], 0.f);
            v0.y = fmaxf(acc[mt][nt][1] + b2s[c + 1], 0.f);
            v1.x = fmaxf(acc[mt][nt][2] + b2s[c], 0.f);
            v1.y = fmaxf(acc[mt][nt][3] + b2s[c + 1], 0.f);
            *(float2*)&outS[r0 * OSTR + c] = v0;
            *(float2*)&outS[(r0 + 8) * OSTR + c] = v1;
        }
    }
    __syncthreads();

    // segmented max over sorted locals: 256 threads, two row-halves per column.
    {
        int c = tid & 127, h = tid >> 7;
        int rs = h * 64, re = rs + 64;
        int cur = -2, s = rs;
        float m = 0.f;
        for (int r = rs; r < re; r++) {
            int l = lidS[r];
            float v = outS[r * OSTR + c];
            if (l != cur) {
                if (cur >= 0) {
                    float* dst = &g_shape_max[(size_t)cur * CC + c];
                    if (s > rs) *dst = m;
                    else atomicMax((int*)dst, __float_as_int(m));
                }
                cur = l; m = v; s = r;
            } else m = fmaxf(m, v);
        }
        if (cur >= 0)
            atomicMax((int*)&g_shape_max[(size_t)cur * CC + c], __float_as_int(m));
    }
}

// ---------------- launch 5: fg_feat segmax + locals_feat + global key-max (+replay re-zero) ----------------
__global__ void k_featmax(const float* __restrict__ feat, const int* __restrict__ i2l, int L) {
    int gt = blockIdx.x * blockDim.x + threadIdx.x;
    int stride = gridDim.x * blockDim.x;
    for (int i = gt; i < L; i += stride) g_cnt[i] = 0;
    for (int i = gt; i < 3 * L; i += stride) g_sum[i] = 0.f;

    int w = gt >> 5, lane = gt & 31;
    if (w >= L) return;
    int s = g_off[w], e = g_off[w + 1];
    float m0 = -CUDART_INF_F, m1 = m0, m2 = m0, m3 = m0;
    for (int p = s; p < e; p++) {
        const float* row = feat + (size_t)g_pids[p] * CC;
        m0 = fmaxf(m0, row[lane]);
        m1 = fmaxf(m1, row[lane + 32]);
        m2 = fmaxf(m2, row[lane + 64]);
        m3 = fmaxf(m3, row[lane + 96]);
    }
    if (e <= s) { m0 = m1 = m2 = m3 = 0.f; }
    size_t base = (size_t)w * CC;
    float v0 = m0 + g_shape_max[base + lane];
    float v1 = m1 + g_shape_max[base + lane + 32];
    float v2 = m2 + g_shape_max[base + lane + 64];
    float v3 = m3 + g_shape_max[base + lane + 96];
    g_locals_feat[base + lane]      = v0;
    g_locals_feat[base + lane + 32] = v1;
    g_locals_feat[base + lane + 64] = v2;
    g_locals_feat[base + lane + 96] = v3;
    int inst = i2l[w];
    size_t gb = (size_t)inst * CC;
    atomicMax(&g_gkeys[gb + lane],      fkey(v0));
    atomicMax(&g_gkeys[gb + lane + 32], fkey(v1));
    atomicMax(&g_gkeys[gb + lane + 64], fkey(v2));
    atomicMax(&g_gkeys[gb + lane + 96], fkey(v3));
    if (lane == 0) atomicAdd(&g_cnt_i[inst], 1);
}

// ---------------- launch 6: finalize globals + target centers ----------------
__global__ void k_gfin(const int* __restrict__ ils, int I) {
    int idx = blockIdx.x * blockDim.x + threadIdx.x;
    if (idx < I * CC) {
        int i = idx >> 7;
        g_globals[idx] = (g_cnt_i[i] > 0) ? funkey(g_gkeys[idx]) : 0.f;
    }
    if (idx < I * 3) {
        int i = idx / 3, d = idx % 3;
        g_gtlc[idx] = g_centroid[ils[i] * 3 + d];
    }
}

// ---------------- launch 7: locals MLP, 64 locals/block, 3 blocks/SM ----------------
// smem: A1 half[64][280] (35840) | B1c half[128][152] (38912) | b1L,b2L f32[128] + ilS int[64] (1280)
// overlays: hA2 half[64][136] on A1, W2s half[128][136] on B1c, foS f32[64][133] on A1
#define TM 64
#define KF 262
#define KP 272
#define STRL 280
#define STRB 152
#define KCH0 144
#define STRH2 136
#define SH_MLP2 (TM * STRL * 2 + 128 * STRB * 2 + 1280)

__global__ __launch_bounds__(256, 3) void k_mlp2(
    const float* __restrict__ b1, const float* __restrict__ b2,
    const float* __restrict__ Wd, const float* __restrict__ bd,
    const int* __restrict__ i2l,
    float* __restrict__ out_tf, float* __restrict__ out_fo, int L)
{
    extern __shared__ char smraw[];
    __half* A1  = (__half*)smraw;                        // [64][STRL]
    __half* B1c = (__half*)(smraw + TM * STRL * 2);      // [128][STRB]
    float*  ext = (float*)(smraw + TM * STRL * 2 + 128 * STRB * 2);
    float* b1L = ext;            // 128
    float* b2L = ext + 128;      // 128
    int*   ilS = (int*)(ext + 256);  // 64
    __half* hA2 = (__half*)smraw;                        // [64][136] (phase 2)
    __half* W2s = B1c;                                   // [128][136] (phase 2)
    float*  foS = (float*)smraw;                         // [64][133] (phase 3)

    int tid = threadIdx.x;
    int block0 = blockIdx.x * TM;

    if (tid < 128) {
        b1L[tid] = b1[tid];
        b2L[tid] = b2[tid];
    }
    if (tid < TM) {
        int l = block0 + tid;
        ilS[tid] = (l < L) ? i2l[l] : 0;
    }
    __syncthreads();

    // assemble feat fp16 into A1[p][k]; load B chunk 0 (k 0..143)
    for (int idx = tid; idx < TM * KP; idx += 256) {
        int p = idx / KP, k = idx - p * KP;
        int l = block0 + p;
        float v = 0.f;
        if (l < L && k < KF) {
            int inst = ilS[p];
            if (k < 128)       v = g_locals_feat[(size_t)l * CC + k];
            else if (k < 256)  v = g_globals[(size_t)inst * CC + (k - 128)];
            else if (k < 259)  v = g_centroid[l * 3 + (k - 256)];
            else               v = g_gtlc[inst * 3 + (k - 259)];
        }
        A1[p * STRL + k] = __float2half(v);
    }
    {
        const unsigned* src = (const unsigned*)g_W1lt;   // [h][272] halves = [h][136] uints
        for (int i = tid; i < 128 * 72; i += 256) {
            int h = i / 72, j = i - h * 72;
            *(unsigned*)&B1c[h * STRB + j * 2] = src[h * 136 + j];
        }
    }
    __syncthreads();

    int wid = tid >> 5, lane = tid & 31;
    int m0 = (wid >> 2) * 32, n0 = (wid & 3) * 32;
    int g = lane >> 2, t4 = (lane & 3) * 2;

    uint32_t A1_s  = (uint32_t)__cvta_generic_to_shared(A1);
    uint32_t B1c_s = (uint32_t)__cvta_generic_to_shared(B1c);
    uint32_t aOff = ((m0 + (lane & 15)) * STRL + ((lane >> 4) << 3)) * 2;
    uint32_t bOff = ((n0 + ((lane >> 4) << 3) + (lane & 7)) * STRB + (((lane >> 3) & 1) << 3)) * 2;

    float acc[2][4][4];
    #pragma unroll
    for (int a = 0; a < 2; a++)
        #pragma unroll
        for (int b_ = 0; b_ < 4; b_++)
            #pragma unroll
            for (int c = 0; c < 4; c++) acc[a][b_][c] = 0.f;

    // GEMM1 stage 0: k 0..143
    #pragma unroll
    for (int kk = 0; kk < KCH0; kk += 16) {
        unsigned af[2][4];
        ldm_x4(af[0], A1_s + aOff + kk * 2);
        ldm_x4(af[1], A1_s + aOff + kk * 2 + 16 * STRL * 2);
        #pragma unroll
        for (int np = 0; np < 2; np++) {
            unsigned bf[4];
            ldm_x4(bf, B1c_s + bOff + kk * 2 + np * 16 * STRB * 2);
            mma16816(acc[0][2*np],   af[0], bf[0], bf[1]);
            mma16816(acc[1][2*np],   af[1], bf[0], bf[1]);
            mma16816(acc[0][2*np+1], af[0], bf[2], bf[3]);
            mma16816(acc[1][2*np+1], af[1], bf[2], bf[3]);
        }
    }
    __syncthreads();
    // load B chunk 1 (k 144..271 -> 64 uints per row)
    {
        const unsigned* src = (const unsigned*)g_W1lt;
        for (int i = tid; i < 128 * 64; i += 256) {
            int h = i >> 6, j = i & 63;
            *(unsigned*)&B1c[h * STRB + j * 2] = src[h * 136 + 72 + j];
        }
    }
    __syncthreads();
    // GEMM1 stage 1: k 144..271
    #pragma unroll
    for (int kk = 0; kk < KP - KCH0; kk += 16) {
        unsigned af[2][4];
        ldm_x4(af[0], A1_s + aOff + (KCH0 + kk) * 2);
        ldm_x4(af[1], A1_s + aOff + (KCH0 + kk) * 2 + 16 * STRL * 2);
        #pragma unroll
        for (int np = 0; np < 2; np++) {
            unsigned bf[4];
            ldm_x4(bf, B1c_s + bOff + kk * 2 + np * 16 * STRB * 2);
            mma16816(acc[0][2*np],   af[0], bf[0], bf[1]);
            mma16816(acc[1][2*np],   af[1], bf[0], bf[1]);
            mma16816(acc[0][2*np+1], af[0], bf[2], bf[3]);
            mma16816(acc[1][2*np+1], af[1], bf[2], bf[3]);
        }
    }
    __syncthreads();  // A1/B1c reads done -> overlays

    // epilogue 1: relu(acc + b1) -> hA2 fp16; copy W2lt into W2s
    #pragma unroll
    for (int mt = 0; mt < 2; mt++) {
        #pragma unroll
        for (int nt = 0; nt < 4; nt++) {
            int r0 = m0 + mt * 16 + g;
            int c = n0 + nt * 8 + t4;
            float h00 = fmaxf(acc[mt][nt][0] + b1L[c], 0.f);
            float h01 = fmaxf(acc[mt][nt][1] + b1L[c + 1], 0.f);
            float h10 = fmaxf(acc[mt][nt][2] + b1L[c], 0.f);
            float h11 = fmaxf(acc[mt][nt][3] + b1L[c + 1], 0.f);
            *(__half2*)&hA2[r0 * STRH2 + c] = __floats2half2_rn(h00, h01);
            *(__half2*)&hA2[(r0 + 8) * STRH2 + c] = __floats2half2_rn(h10, h11);
        }
    }
    {
        const unsigned* src = (const unsigned*)g_W2lt;
        for (int i = tid; i < 8192; i += 256) {
            int c = i >> 6, k2 = (i & 63) << 1;
            *(unsigned*)&W2s[c * STRH2 + k2] = src[i];
        }
    }
    __syncthreads();

    // GEMM2: [64 x 128] = hA2[64 x 128] * W2lt^T, K=128
    #pragma unroll
    for (int a = 0; a < 2; a++)
        #pragma unroll
        for (int b_ = 0; b_ < 4; b_++)
            #pragma unroll
            for (int c = 0; c < 4; c++) acc[a][b_][c] = 0.f;

    uint32_t hA2_s = (uint32_t)__cvta_generic_to_shared(hA2);
    uint32_t W2s_s = (uint32_t)__cvta_generic_to_shared(W2s);
    uint32_t aOff2 = ((m0 + (lane & 15)) * STRH2 + ((lane >> 4) << 3)) * 2;
    uint32_t bOff2 = ((n0 + ((lane >> 4) << 3) + (lane & 7)) * STRH2 + (((lane >> 3) & 1) << 3)) * 2;

    #pragma unroll
    for (int kk = 0; kk < 128; kk += 16) {
        unsigned af[2][4];
        ldm_x4(af[0], hA2_s + aOff2 + kk * 2);
        ldm_x4(af[1], hA2_s + aOff2 + kk * 2 + 16 * STRH2 * 2);
        #pragma unroll
        for (int np = 0; np < 2; np++) {
            unsigned bf[4];
            ldm_x4(bf, W2s_s + bOff2 + kk * 2 + np * 16 * STRH2 * 2);
            mma16816(acc[0][2*np],   af[0], bf[0], bf[1]);
            mma16816(acc[1][2*np],   af[1], bf[0], bf[1]);
            mma16816(acc[0][2*np+1], af[0], bf[2], bf[3]);
            mma16816(acc[1][2*np+1], af[1], bf[2], bf[3]);
        }
    }
    __syncthreads();  // hA2/W2s reads done -> foS

    // epilogue 2: relu(acc + b2) -> out_fo + foS
    #pragma unroll
    for (int mt = 0; mt < 2; mt++) {
        #pragma unroll
        for (int nt = 0; nt < 4; nt++) {
            int r0 = m0 + mt * 16 + g;
            int c = n0 + nt * 8 + t4;
            float v00 = fmaxf(acc[mt][nt][0] + b2L[c], 0.f);
            float v01 = fmaxf(acc[mt][nt][1] + b2L[c + 1], 0.f);
            float v10 = fmaxf(acc[mt][nt][2] + b2L[c], 0.f);
            float v11 = fmaxf(acc[mt][nt][3] + b2L[c + 1], 0.f);
            foS[r0 * 133 + c] = v00; foS[r0 * 133 + c + 1] = v01;
            foS[(r0 + 8) * 133 + c] = v10; foS[(r0 + 8) * 133 + c + 1] = v11;
            int l0 = block0 + r0, l1 = block0 + r0 + 8;
            if (l0 < L) { float2 s; s.x = v00; s.y = v01; *(float2*)&out_fo[(size_t)l0 * CC + c] = s; }
            if (l1 < L) { float2 s; s.x = v10; s.y = v11; *(float2*)&out_fo[(size_t)l1 * CC + c] = s; }
        }
    }
    __syncthreads();

    // decoder: Wd/bd from gmem (L2-hot)
    if (tid < TM) {
        int l = block0 + tid;
        if (l < L) {
            float s[7];
            #pragma unroll
            for (int j = 0; j < 7; j++) s[j] = bd[j];
            for (int c = 0; c < 128; c++) {
                float f = foS[tid * 133 + c];
                #pragma unroll
                for (int j = 0; j < 7; j++) s[j] = fmaf(f, Wd[c * 7 + j], s[j]);
            }
            #pragma unroll
            for (int j = 0; j < 7; j++) out_tf[(size_t)l * 7 + j] = s[j];
        }
    }
}

// ---------------- launch ----------------
extern "C" void kernel_launch(void* const* d_in, const int* in_sizes, int n_in,
                              void* d_out, int out_size) {
    const float* xyz  = (const float*)d_in[0];
    const float* feat = (const float*)d_in[1];
    const float* W1s_ = (const float*)d_in[2];
    const float* b1s_ = (const float*)d_in[3];
    const float* W2s_ = (const float*)d_in[4];
    const float* b2s_ = (const float*)d_in[5];
    const float* W1l  = (const float*)d_in[6];
    const float* b1l  = (const float*)d_in[7];
    const float* W2l  = (const float*)d_in[8];
    const float* b2l  = (const float*)d_in[9];
    const float* Wd   = (const float*)d_in[10];
    const float* bd   = (const float*)d_in[11];
    const int*   l2f  = (const int*)d_in[12];
    const int*   i2l  = (const int*)d_in[13];
    const int*   ils  = (const int*)d_in[14];

    int n = in_sizes[0] / 3;
    int L = in_sizes[13];
    int I = in_sizes[14];

    float* out_tf = (float*)d_out;
    float* out_fo = (float*)d_out + (size_t)L * 7;

    cudaFuncSetAttribute(k_shape, cudaFuncAttributeMaxDynamicSharedMemorySize, SH_SHAPE);
    cudaFuncSetAttribute(k_mlp2,  cudaFuncAttributeMaxDynamicSharedMemorySize, SH_MLP2);

    // g_cnt/g_sum zero at first call (static init); re-zeroed in k_featmax each pass.
    k_count<<<(n + 255) / 256, 256>>>(xyz, l2f, n);                                       // 1
    k_scan<<<1, 1024>>>(L);                                                               // 2
    k_csr<<<(n + 255) / 256, 256>>>(l2f, W2s_, W1l, W2l, n, L, I);                        // 3
    k_shape<<<(n + 127) / 128, 256, SH_SHAPE>>>(xyz, W1s_, b1s_, b2s_, n);                // 4 <- profiled
    k_featmax<<<(L * 32 + 255) / 256, 256>>>(feat, i2l, L);                               // 5
    k_gfin<<<(I * CC + 255) / 256, 256>>>(ils, I);                                        // 6
    k_mlp2<<<(L + TM - 1) / TM, 256, SH_MLP2>>>(b1l, b2l, Wd, bd, i2l, out_tf, out_fo, L); // 7
}

// round 17
// speedup vs baseline: 1.5415x; 1.0044x over previous
#include <cuda_runtime.h>
#include <cuda_fp16.h>
#include <math_constants.h>
#include <stdint.h>

#define LMAX 100000
#define IMAX 10000
#define NMAX 1000000
#define CC 128

// ---------------- static device scratch (zero-initialized at module load) ----------------
__device__ int      g_cnt[LMAX];
__device__ float    g_sum[LMAX * 3];
__device__ float    g_centroid[LMAX * 3];
__device__ int      g_off[LMAX + 1];
__device__ int      g_cursor[LMAX];
__device__ int      g_pids[NMAX];
__device__ int      g_plocal[NMAX];
__device__ float    g_shape_max[(size_t)LMAX * CC];
__device__ float    g_locals_feat[(size_t)LMAX * CC];
__device__ int      g_cnt_i[IMAX];
__device__ unsigned g_gkeys[(size_t)IMAX * CC];
__device__ float    g_gtlc[IMAX * 3];
__device__ float    g_globals[(size_t)IMAX * CC];
__device__ __half   g_W2t[128 * 128];     // W2_shape^T fp16: [c][k] linear
__device__ __half   g_W1lt[128 * 272];    // W1_loc^T fp16, K padded 262->272: [h][k]
__device__ __half   g_W2lt[128 * 128];    // W2_loc^T fp16: [c][k]

// order-preserving float->uint key for atomicMax on signed floats.
__device__ __forceinline__ unsigned fkey(float f) {
    unsigned b = __float_as_uint(f);
    return (b & 0x80000000u) ? ~b : (b | 0x80000000u);
}
__device__ __forceinline__ float funkey(unsigned k) {
    return (k & 0x80000000u) ? __uint_as_float(k & 0x7fffffffu) : __uint_as_float(~k);
}

// ---------------- launch 1: centroid count + sum ----------------
__global__ void k_count(const float* __restrict__ xyz, const int* __restrict__ l2f, int n) {
    int i = blockIdx.x * blockDim.x + threadIdx.x;
    if (i >= n) return;
    int l = l2f[i];
    atomicAdd(&g_cnt[l], 1);
    atomicAdd(&g_sum[l * 3 + 0], xyz[i * 3 + 0]);
    atomicAdd(&g_sum[l * 3 + 1], xyz[i * 3 + 1]);
    atomicAdd(&g_sum[l * 3 + 2], xyz[i * 3 + 2]);
}

// ---------------- launch 2: exclusive scan of g_cnt + cursor zero (single block) ----------------
__global__ void k_scan(int L) {
    __shared__ int wsum[32];
    int tid = threadIdx.x;                 // 1024 threads
    for (int l = tid; l < L; l += 1024) g_cursor[l] = 0;

    int chunk = (L + 1023) >> 10;
    int s = tid * chunk;
    int e = s + chunk; if (e > L) e = L;
    if (s > L) s = L;
    int sum = 0;
    for (int i = s; i < e; i++) sum += g_cnt[i];

    int lane = tid & 31, w = tid >> 5;
    int v = sum;
    #pragma unroll
    for (int o = 1; o < 32; o <<= 1) {
        int t = __shfl_up_sync(0xffffffffu, v, o);
        if (lane >= o) v += t;
    }
    if (lane == 31) wsum[w] = v;
    __syncthreads();
    if (w == 0) {
        int x = wsum[lane];
        #pragma unroll
        for (int o = 1; o < 32; o <<= 1) {
            int t = __shfl_up_sync(0xffffffffu, x, o);
            if (lane >= o) x += t;
        }
        wsum[lane] = x;
    }
    __syncthreads();
    int excl = v - sum + (w > 0 ? wsum[w - 1] : 0);
    int run = excl;
    for (int i = s; i < e; i++) { int c = g_cnt[i]; g_off[i] = run; run += c; }
    if (tid == 1023) g_off[L] = run;
}

// ---------------- launch 3: CSR scatter + centroid + weight prep + zero (wide grid) ----------------
__global__ void k_csr(const int* __restrict__ l2f,
                      const float* __restrict__ W2s_, const float* __restrict__ W1l,
                      const float* __restrict__ W2l,
                      int n, int L, int I) {
    int gt = blockIdx.x * blockDim.x + threadIdx.x;
    int stride = gridDim.x * blockDim.x;

    for (int i = gt; i < 16384; i += stride) {
        int c = i >> 7, k = i & 127;
        g_W2t[i]  = __float2half(W2s_[k * 128 + c]);
        g_W2lt[i] = __float2half(W2l[k * 128 + c]);
    }
    for (int i = gt; i < 128 * 272; i += stride) {
        int h = i / 272, k = i - h * 272;
        g_W1lt[i] = (k < 262) ? __float2half(W1l[k * 128 + h]) : __half(0.f);
    }
    for (int l = gt; l < L; l += stride) {
        float inv = 1.f / fmaxf((float)g_cnt[l], 1.f);
        g_centroid[l * 3 + 0] = g_sum[l * 3 + 0] * inv;
        g_centroid[l * 3 + 1] = g_sum[l * 3 + 1] * inv;
        g_centroid[l * 3 + 2] = g_sum[l * 3 + 2] * inv;
    }
    for (int i = gt; i < L * CC; i += stride) g_shape_max[i] = 0.f;
    for (int i = gt; i < I * CC; i += stride) g_gkeys[i] = 0u;
    for (int i = gt; i < I; i += stride) g_cnt_i[i] = 0;
    if (gt < n) {
        int l = l2f[gt];
        int pos = atomicAdd(&g_cursor[l], 1);
        int slot = g_off[l] + pos;
        g_pids[slot] = gt;
        g_plocal[slot] = l;
    }
}

// ---------------- mma / ldmatrix helpers ----------------
__device__ __forceinline__ void mma16816(float* d, const unsigned* a, unsigned b0, unsigned b1) {
    asm volatile(
        "mma.sync.aligned.m16n8k16.row.col.f32.f16.f16.f32 "
        "{%0,%1,%2,%3}, {%4,%5,%6,%7}, {%8,%9}, {%0,%1,%2,%3};"
        : "+f"(d[0]), "+f"(d[1]), "+f"(d[2]), "+f"(d[3])
        : "r"(a[0]), "r"(a[1]), "r"(a[2]), "r"(a[3]), "r"(b0), "r"(b1));
}
__device__ __forceinline__ void ldm_x4(unsigned* r, uint32_t saddr) {
    asm volatile(
        "ldmatrix.sync.aligned.m8n8.x4.shared.b16 {%0,%1,%2,%3}, [%4];"
        : "=r"(r[0]), "=r"(r[1]), "=r"(r[2]), "=r"(r[3]) : "r"(saddr));
}

// ---------------- launch 4 (profiled): shape MLP, 64 points/block, 4 blocks/SM ----------------
// smem: hA half[64][136] (17408) | W2t half[128][136] (34816)  [outS f32[64][136] overlays]
//       cS float4[64] (1024) | b2s f32[128] (512) | lidS int[64] (256)
#define TMS 64
#define STRH 136
#define OSTR 136
#define SH_SHAPE (TMS * STRH * 2 + 128 * STRH * 2 + 1024 + 512 + 256)

__global__ __launch_bounds__(256, 4) void k_shape(
    const float* __restrict__ xyz,
    const float* __restrict__ W1, const float* __restrict__ b1,
    const float* __restrict__ b2, int n)
{
    extern __shared__ char smraw[];
    __half* hA  = (__half*)smraw;                        // [64][STRH]
    __half* W2t = (__half*)(smraw + TMS * STRH * 2);     // [128][STRH]
    float*  outS = (float*)smraw;                        // overlay, [64][OSTR]
    float*  cS  = (float*)(smraw + TMS * STRH * 2 + 128 * STRH * 2);
    float*  b2s = cS + TMS * 4;
    int*   lidS = (int*)(b2s + 128);

    int tid = threadIdx.x;
    int tile0 = blockIdx.x * TMS;

    // phase A: coords gather (tid<64) + b2 (tid<128) || W2t smem copy (tid>=128)
    if (tid < 128) {
        b2s[tid] = b2[tid];
        if (tid < TMS) {
            int p = tid;
            int row = tile0 + p;
            float cx = 0.f, cy = 0.f, cz = 0.f;
            int l = -1;
            if (row < n) {
                int pid = g_pids[row];
                l = g_plocal[row];
                cx = xyz[pid * 3 + 0] - g_centroid[l * 3 + 0];
                cy = xyz[pid * 3 + 1] - g_centroid[l * 3 + 1];
                cz = xyz[pid * 3 + 2] - g_centroid[l * 3 + 2];
            }
            float4 c4; c4.x = cx; c4.y = cy; c4.z = cz; c4.w = 0.f;
            *(float4*)&cS[p * 4] = c4;
            lidS[p] = l;
        }
    } else {
        int t = tid - 128;
        const unsigned* src = (const unsigned*)g_W2t;
        for (int i = t; i < 8192; i += 128) {
            int c = i >> 6, k2 = (i & 63) << 1;
            *(unsigned*)&W2t[c * STRH + k2] = src[i];
        }
    }
    __syncthreads();

    // phase B: layer1, lanes on k (conflict-free stores), weights in registers.
    {
        int k = (tid & 63) * 2;       // this thread's two k's
        int p0 = (tid >> 6) * 16;     // 16-point group
        float w0x = W1[k],       w1x = W1[k + 1];
        float w0y = W1[128 + k], w1y = W1[129 + k];
        float w0z = W1[256 + k], w1z = W1[257 + k];
        float bb0 = b1[k],       bb1 = b1[k + 1];
        #pragma unroll 8
        for (int pp = 0; pp < 16; pp++) {
            int p = p0 + pp;
            float4 c4 = *(const float4*)&cS[p * 4];
            float h0 = fmaf(c4.x, w0x, fmaf(c4.y, w0y, fmaf(c4.z, w0z, bb0)));
            float h1 = fmaf(c4.x, w1x, fmaf(c4.y, w1y, fmaf(c4.z, w1z, bb1)));
            h0 = fmaxf(h0, 0.f);
            h1 = fmaxf(h1, 0.f);
            *(__half2*)&hA[p * STRH + k] = __floats2half2_rn(h0, h1);
        }
    }
    __syncthreads();

    // tensor-core GEMM: 64x128x128, warps 2(m) x 4(n), ldmatrix fragment loads
    int wid = tid >> 5, lane = tid & 31;
    int m0 = (wid >> 2) * 32, n0 = (wid & 3) * 32;
    int g = lane >> 2, t4 = (lane & 3) * 2;

    uint32_t hA_s  = (uint32_t)__cvta_generic_to_shared(hA);
    uint32_t W2t_s = (uint32_t)__cvta_generic_to_shared(W2t);
    uint32_t aAddr = hA_s  + ((m0 + (lane & 15)) * STRH + ((lane >> 4) << 3)) * 2;
    uint32_t bAddr = W2t_s + ((n0 + ((lane >> 4) << 3) + (lane & 7)) * STRH + (((lane >> 3) & 1) << 3)) * 2;

    float acc[2][4][4];
    #pragma unroll
    for (int a = 0; a < 2; a++)
        #pragma unroll
        for (int b_ = 0; b_ < 4; b_++)
            #pragma unroll
            for (int c = 0; c < 4; c++) acc[a][b_][c] = 0.f;

    #pragma unroll
    for (int kk = 0; kk < 128; kk += 16) {
        unsigned af[2][4];
        ldm_x4(af[0], aAddr + kk * 2);
        ldm_x4(af[1], aAddr + kk * 2 + 16 * STRH * 2);
        #pragma unroll
        for (int np = 0; np < 2; np++) {
            unsigned bf[4];
            ldm_x4(bf, bAddr + kk * 2 + np * 16 * STRH * 2);
            mma16816(acc[0][2*np],   af[0], bf[0], bf[1]);
            mma16816(acc[1][2*np],   af[1], bf[0], bf[1]);
            mma16816(acc[0][2*np+1], af[0], bf[2], bf[3]);
            mma16816(acc[1][2*np+1], af[1], bf[2], bf[3]);
        }
    }
    __syncthreads();   // done reading hA/W2t -> reuse as outS

    #pragma unroll
    for (int mt = 0; mt < 2; mt++) {
        #pragma unroll
        for (int nt = 0; nt < 4; nt++) {
            int r0 = m0 + mt * 16 + g;
            int c = n0 + nt * 8 + t4;
            float2 v0, v1;
            v0.x = fmaxf(acc[mt][nt][0] + b2s[c], 0.f);
            v0.y = fmaxf(acc[mt][nt][1] + b2s[c + 1], 0.f);
            v1.x = fmaxf(acc[mt][nt][2] + b2s[c], 0.f);
            v1.y = fmaxf(acc[mt][nt][3] + b2s[c + 1], 0.f);
            *(float2*)&outS[r0 * OSTR + c] = v0;
            *(float2*)&outS[(r0 + 8) * OSTR + c] = v1;
        }
    }
    __syncthreads();

    // segmented max over sorted locals: 256 threads, two 32-row halves per column.
    {
        int c = tid & 127, h = tid >> 7;
        int rs = h * 32, re = rs + 32;
        int cur = -2, s = rs;
        float m = 0.f;
        for (int r = rs; r < re; r++) {
            int l = lidS[r];
            float v = outS[r * OSTR + c];
            if (l != cur) {
                if (cur >= 0) {
                    float* dst = &g_shape_max[(size_t)cur * CC + c];
                    if (s > rs) *dst = m;
                    else atomicMax((int*)dst, __float_as_int(m));
                }
                cur = l; m = v; s = r;
            } else m = fmaxf(m, v);
        }
        if (cur >= 0)
            atomicMax((int*)&g_shape_max[(size_t)cur * CC + c], __float_as_int(m));
    }
}

// ---------------- launch 5: fg_feat segmax + locals_feat + global key-max (+replay re-zero) ----------------
__global__ void k_featmax(const float* __restrict__ feat, const int* __restrict__ i2l, int L) {
    int gt = blockIdx.x * blockDim.x + threadIdx.x;
    int stride = gridDim.x * blockDim.x;
    for (int i = gt; i < L; i += stride) g_cnt[i] = 0;
    for (int i = gt; i < 3 * L; i += stride) g_sum[i] = 0.f;

    int w = gt >> 5, lane = gt & 31;
    if (w >= L) return;
    int s = g_off[w], e = g_off[w + 1];
    float m0 = -CUDART_INF_F, m1 = m0, m2 = m0, m3 = m0;
    for (int p = s; p < e; p++) {
        const float* row = feat + (size_t)g_pids[p] * CC;
        m0 = fmaxf(m0, row[lane]);
        m1 = fmaxf(m1, row[lane + 32]);
        m2 = fmaxf(m2, row[lane + 64]);
        m3 = fmaxf(m3, row[lane + 96]);
    }
    if (e <= s) { m0 = m1 = m2 = m3 = 0.f; }
    size_t base = (size_t)w * CC;
    float v0 = m0 + g_shape_max[base + lane];
    float v1 = m1 + g_shape_max[base + lane + 32];
    float v2 = m2 + g_shape_max[base + lane + 64];
    float v3 = m3 + g_shape_max[base + lane + 96];
    g_locals_feat[base + lane]      = v0;
    g_locals_feat[base + lane + 32] = v1;
    g_locals_feat[base + lane + 64] = v2;
    g_locals_feat[base + lane + 96] = v3;
    int inst = i2l[w];
    size_t gb = (size_t)inst * CC;
    atomicMax(&g_gkeys[gb + lane],      fkey(v0));
    atomicMax(&g_gkeys[gb + lane + 32], fkey(v1));
    atomicMax(&g_gkeys[gb + lane + 64], fkey(v2));
    atomicMax(&g_gkeys[gb + lane + 96], fkey(v3));
    if (lane == 0) atomicAdd(&g_cnt_i[inst], 1);
}

// ---------------- launch 6: finalize globals + target centers ----------------
__global__ void k_gfin(const int* __restrict__ ils, int I) {
    int idx = blockIdx.x * blockDim.x + threadIdx.x;
    if (idx < I * CC) {
        int i = idx >> 7;
        g_globals[idx] = (g_cnt_i[i] > 0) ? funkey(g_gkeys[idx]) : 0.f;
    }
    if (idx < I * 3) {
        int i = idx / 3, d = idx % 3;
        g_gtlc[idx] = g_centroid[ils[i] * 3 + d];
    }
}

// ---------------- launch 7: locals MLP, 64 locals/block, 3 blocks/SM ----------------
#define TM 64
#define KF 262
#define KP 272
#define STRL 280
#define STRB 152
#define KCH0 144
#define STRH2 136
#define SH_MLP2 (TM * STRL * 2 + 128 * STRB * 2 + 1280)

__global__ __launch_bounds__(256, 3) void k_mlp2(
    const float* __restrict__ b1, const float* __restrict__ b2,
    const float* __restrict__ Wd, const float* __restrict__ bd,
    const int* __restrict__ i2l,
    float* __restrict__ out_tf, float* __restrict__ out_fo, int L)
{
    extern __shared__ char smraw[];
    __half* A1  = (__half*)smraw;                        // [64][STRL]
    __half* B1c = (__half*)(smraw + TM * STRL * 2);      // [128][STRB]
    float*  ext = (float*)(smraw + TM * STRL * 2 + 128 * STRB * 2);
    float* b1L = ext;            // 128
    float* b2L = ext + 128;      // 128
    int*   ilS = (int*)(ext + 256);  // 64
    __half* hA2 = (__half*)smraw;                        // [64][136] (phase 2)
    __half* W2s = B1c;                                   // [128][136] (phase 2)
    float*  foS = (float*)smraw;                         // [64][133] (phase 3)

    int tid = threadIdx.x;
    int block0 = blockIdx.x * TM;

    if (tid < 128) {
        b1L[tid] = b1[tid];
        b2L[tid] = b2[tid];
    }
    if (tid < TM) {
        int l = block0 + tid;
        ilS[tid] = (l < L) ? i2l[l] : 0;
    }
    __syncthreads();

    for (int idx = tid; idx < TM * KP; idx += 256) {
        int p = idx / KP, k = idx - p * KP;
        int l = block0 + p;
        float v = 0.f;
        if (l < L && k < KF) {
            int inst = ilS[p];
            if (k < 128)       v = g_locals_feat[(size_t)l * CC + k];
            else if (k < 256)  v = g_globals[(size_t)inst * CC + (k - 128)];
            else if (k < 259)  v = g_centroid[l * 3 + (k - 256)];
            else               v = g_gtlc[inst * 3 + (k - 259)];
        }
        A1[p * STRL + k] = __float2half(v);
    }
    {
        const unsigned* src = (const unsigned*)g_W1lt;   // [h][272] halves = [h][136] uints
        for (int i = tid; i < 128 * 72; i += 256) {
            int h = i / 72, j = i - h * 72;
            *(unsigned*)&B1c[h * STRB + j * 2] = src[h * 136 + j];
        }
    }
    __syncthreads();

    int wid = tid >> 5, lane = tid & 31;
    int m0 = (wid >> 2) * 32, n0 = (wid & 3) * 32;
    int g = lane >> 2, t4 = (lane & 3) * 2;

    uint32_t A1_s  = (uint32_t)__cvta_generic_to_shared(A1);
    uint32_t B1c_s = (uint32_t)__cvta_generic_to_shared(B1c);
    uint32_t aOff = ((m0 + (lane & 15)) * STRL + ((lane >> 4) << 3)) * 2;
    uint32_t bOff = ((n0 + ((lane >> 4) << 3) + (lane & 7)) * STRB + (((lane >> 3) & 1) << 3)) * 2;

    float acc[2][4][4];
    #pragma unroll
    for (int a = 0; a < 2; a++)
        #pragma unroll
        for (int b_ = 0; b_ < 4; b_++)
            #pragma unroll
            for (int c = 0; c < 4; c++) acc[a][b_][c] = 0.f;

    // GEMM1 stage 0: k 0..143
    #pragma unroll
    for (int kk = 0; kk < KCH0; kk += 16) {
        unsigned af[2][4];
        ldm_x4(af[0], A1_s + aOff + kk * 2);
        ldm_x4(af[1], A1_s + aOff + kk * 2 + 16 * STRL * 2);
        #pragma unroll
        for (int np = 0; np < 2; np++) {
            unsigned bf[4];
            ldm_x4(bf, B1c_s + bOff + kk * 2 + np * 16 * STRB * 2);
            mma16816(acc[0][2*np],   af[0], bf[0], bf[1]);
            mma16816(acc[1][2*np],   af[1], bf[0], bf[1]);
            mma16816(acc[0][2*np+1], af[0], bf[2], bf[3]);
            mma16816(acc[1][2*np+1], af[1], bf[2], bf[3]);
        }
    }
    __syncthreads();
    {
        const unsigned* src = (const unsigned*)g_W1lt;
        for (int i = tid; i < 128 * 64; i += 256) {
            int h = i >> 6, j = i & 63;
            *(unsigned*)&B1c[h * STRB + j * 2] = src[h * 136 + 72 + j];
        }
    }
    __syncthreads();
    // GEMM1 stage 1: k 144..271
    #pragma unroll
    for (int kk = 0; kk < KP - KCH0; kk += 16) {
        unsigned af[2][4];
        ldm_x4(af[0], A1_s + aOff + (KCH0 + kk) * 2);
        ldm_x4(af[1], A1_s + aOff + (KCH0 + kk) * 2 + 16 * STRL * 2);
        #pragma unroll
        for (int np = 0; np < 2; np++) {
            unsigned bf[4];
            ldm_x4(bf, B1c_s + bOff + kk * 2 + np * 16 * STRB * 2);
            mma16816(acc[0][2*np],   af[0], bf[0], bf[1]);
            mma16816(acc[1][2*np],   af[1], bf[0], bf[1]);
            mma16816(acc[0][2*np+1], af[0], bf[2], bf[3]);
            mma16816(acc[1][2*np+1], af[1], bf[2], bf[3]);
        }
    }
    __syncthreads();  // A1/B1c reads done -> overlays

    // epilogue 1: relu(acc + b1) -> hA2 fp16; copy W2lt into W2s
    #pragma unroll
    for (int mt = 0; mt < 2; mt++) {
        #pragma unroll
        for (int nt = 0; nt < 4; nt++) {
            int r0 = m0 + mt * 16 + g;
            int c = n0 + nt * 8 + t4;
            float h00 = fmaxf(acc[mt][nt][0] + b1L[c], 0.f);
            float h01 = fmaxf(acc[mt][nt][1] + b1L[c + 1], 0.f);
            float h10 = fmaxf(acc[mt][nt][2] + b1L[c], 0.f);
            float h11 = fmaxf(acc[mt][nt][3] + b1L[c + 1], 0.f);
            *(__half2*)&hA2[r0 * STRH2 + c] = __floats2half2_rn(h00, h01);
            *(__half2*)&hA2[(r0 + 8) * STRH2 + c] = __floats2half2_rn(h10, h11);
        }
    }
    {
        const unsigned* src = (const unsigned*)g_W2lt;
        for (int i = tid; i < 8192; i += 256) {
            int c = i >> 6, k2 = (i & 63) << 1;
            *(unsigned*)&W2s[c * STRH2 + k2] = src[i];
        }
    }
    __syncthreads();

    // GEMM2: [64 x 128] = hA2[64 x 128] * W2lt^T, K=128
    #pragma unroll
    for (int a = 0; a < 2; a++)
        #pragma unroll
        for (int b_ = 0; b_ < 4; b_++)
            #pragma unroll
            for (int c = 0; c < 4; c++) acc[a][b_][c] = 0.f;

    uint32_t hA2_s = (uint32_t)__cvta_generic_to_shared(hA2);
    uint32_t W2s_s = (uint32_t)__cvta_generic_to_shared(W2s);
    uint32_t aOff2 = ((m0 + (lane & 15)) * STRH2 + ((lane >> 4) << 3)) * 2;
    uint32_t bOff2 = ((n0 + ((lane >> 4) << 3) + (lane & 7)) * STRH2 + (((lane >> 3) & 1) << 3)) * 2;

    #pragma unroll
    for (int kk = 0; kk < 128; kk += 16) {
        unsigned af[2][4];
        ldm_x4(af[0], hA2_s + aOff2 + kk * 2);
        ldm_x4(af[1], hA2_s + aOff2 + kk * 2 + 16 * STRH2 * 2);
        #pragma unroll
        for (int np = 0; np < 2; np++) {
            unsigned bf[4];
            ldm_x4(bf, W2s_s + bOff2 + kk * 2 + np * 16 * STRH2 * 2);
            mma16816(acc[0][2*np],   af[0], bf[0], bf[1]);
            mma16816(acc[1][2*np],   af[1], bf[0], bf[1]);
            mma16816(acc[0][2*np+1], af[0], bf[2], bf[3]);
            mma16816(acc[1][2*np+1], af[1], bf[2], bf[3]);
        }
    }
    __syncthreads();  // hA2/W2s reads done -> foS

    // epilogue 2: relu(acc + b2) -> out_fo + foS
    #pragma unroll
    for (int mt = 0; mt < 2; mt++) {
        #pragma unroll
        for (int nt = 0; nt < 4; nt++) {
            int r0 = m0 + mt * 16 + g;
            int c = n0 + nt * 8 + t4;
            float v00 = fmaxf(acc[mt][nt][0] + b2L[c], 0.f);
            float v01 = fmaxf(acc[mt][nt][1] + b2L[c + 1], 0.f);
            float v10 = fmaxf(acc[mt][nt][2] + b2L[c], 0.f);
            float v11 = fmaxf(acc[mt][nt][3] + b2L[c + 1], 0.f);
            foS[r0 * 133 + c] = v00; foS[r0 * 133 + c + 1] = v01;
            foS[(r0 + 8) * 133 + c] = v10; foS[(r0 + 8) * 133 + c + 1] = v11;
            int l0 = block0 + r0, l1 = block0 + r0 + 8;
            if (l0 < L) { float2 s; s.x = v00; s.y = v01; *(float2*)&out_fo[(size_t)l0 * CC + c] = s; }
            if (l1 < L) { float2 s; s.x = v10; s.y = v11; *(float2*)&out_fo[(size_t)l1 * CC + c] = s; }
        }
    }
    __syncthreads();

    // decoder: Wd/bd from gmem (L2-hot)
    if (tid < TM) {
        int l = block0 + tid;
        if (l < L) {
            float s[7];
            #pragma unroll
            for (int j = 0; j < 7; j++) s[j] = bd[j];
            for (int c = 0; c < 128; c++) {
                float f = foS[tid * 133 + c];
                #pragma unroll
                for (int j = 0; j < 7; j++) s[j] = fmaf(f, Wd[c * 7 + j], s[j]);
            }
            #pragma unroll
            for (int j = 0; j < 7; j++) out_tf[(size_t)l * 7 + j] = s[j];
        }
    }
}

// ---------------- launch ----------------
extern "C" void kernel_launch(void* const* d_in, const int* in_sizes, int n_in,
                              void* d_out, int out_size) {
    const float* xyz  = (const float*)d_in[0];
    const float* feat = (const float*)d_in[1];
    const float* W1s_ = (const float*)d_in[2];
    const float* b1s_ = (const float*)d_in[3];
    const float* W2s_ = (const float*)d_in[4];
    const float* b2s_ = (const float*)d_in[5];
    const float* W1l  = (const float*)d_in[6];
    const float* b1l  = (const float*)d_in[7];
    const float* W2l  = (const float*)d_in[8];
    const float* b2l  = (const float*)d_in[9];
    const float* Wd   = (const float*)d_in[10];
    const float* bd   = (const float*)d_in[11];
    const int*   l2f  = (const int*)d_in[12];
    const int*   i2l  = (const int*)d_in[13];
    const int*   ils  = (const int*)d_in[14];

    int n = in_sizes[0] / 3;
    int L = in_sizes[13];
    int I = in_sizes[14];

    float* out_tf = (float*)d_out;
    float* out_fo = (float*)d_out + (size_t)L * 7;

    cudaFuncSetAttribute(k_shape, cudaFuncAttributeMaxDynamicSharedMemorySize, SH_SHAPE);
    cudaFuncSetAttribute(k_mlp2,  cudaFuncAttributeMaxDynamicSharedMemorySize, SH_MLP2);

    // g_cnt/g_sum zero at first call (static init); re-zeroed in k_featmax each pass.
    k_count<<<(n + 255) / 256, 256>>>(xyz, l2f, n);                                        // 1
    k_scan<<<1, 1024>>>(L);                                                                // 2
    k_csr<<<(n + 255) / 256, 256>>>(l2f, W2s_, W1l, W2l, n, L, I);                         // 3
    k_shape<<<(n + TMS - 1) / TMS, 256, SH_SHAPE>>>(xyz, W1s_, b1s_, b2s_, n);             // 4 <- profiled
    k_featmax<<<(L * 32 + 255) / 256, 256>>>(feat, i2l, L);                                // 5
    k_gfin<<<(I * CC + 255) / 256, 256>>>(ils, I);                                         // 6
    k_mlp2<<<(L + TM - 1) / TM, 256, SH_MLP2>>>(b1l, b2l, Wd, bd, i2l, out_tf, out_fo, L); // 7
}